// round 2
// baseline (speedup 1.0000x reference)
#include <cuda_runtime.h>
#include <math.h>

// Problem constants (fixed by setup_inputs)
#define Bsz 64
#define Hd  1024
#define Ed  1024
#define Vv  32000
#define Ll  2
#define Tt  64
#define START_TOK 1

#define BK 64                 // K-chunk per smem tile
#define SCORE_TN 128          // cols per score block
#define NBLK_SCORE (Vv / SCORE_TN)   // 250

// ---------------- persistent device state ----------------
__device__ float g_hbuf[2][Ll][Bsz][Hd];   // ping-pong hidden state
__device__ float g_cbuf[Ll][Bsz][Hd];      // cell state (thread-owned update)
__device__ int   g_xt[Bsz];                // current token
__device__ float g_hid[Bsz][Ed];           // relu(o2emb) activations
__device__ float g_pval[Bsz][NBLK_SCORE];  // per-block argmax partial values
__device__ int   g_pidx[Bsz][NBLK_SCORE];  // per-block argmax partial indices

__device__ __forceinline__ float sigmoidf_(float x) {
    return 1.0f / (1.0f + expf(-x));
}

// ---------------- init: zero state, set start token ----------------
__global__ void init_kernel() {
    int idx = blockIdx.x * blockDim.x + threadIdx.x;
    float* c = &g_cbuf[0][0][0];
    float* h = &g_hbuf[0][0][0][0];
    if (idx < Ll * Bsz * Hd) {
        c[idx] = 0.0f;
        h[idx] = 0.0f;
    }
    if (idx < Bsz) g_xt[idx] = START_TOK;
}

// ---------------- fused LSTM layer: gates GEMM + cell update ----------------
// grid = 128 blocks (8 j-columns each), block = 128 threads.
// Each thread owns 4 rows x 4 gates of one j column -> cell update is thread-local.
// Layer 0 gathers x = emb[xt[b]] directly (no separate embed kernel).
__global__ __launch_bounds__(128) void lstm_kernel(
    const float* __restrict__ emb,
    const float* __restrict__ w_ih_all, const float* __restrict__ w_hh_all,
    const float* __restrict__ b_ih_all, const float* __restrict__ b_hh_all,
    int layer, int parity)
{
    __shared__ float xs[BK][Bsz + 1];   // [k][row], pad -> conflict-free
    __shared__ float ws[BK][32 + 1];    // [k][col], 32 cols = 4 gates x 8 j
    __shared__ int   toks[Bsz];

    const int tid = threadIdx.x;
    const int j0  = blockIdx.x * 8;
    const int cg  = tid & 7;     // j within tile
    const int rg  = tid >> 3;    // row group (16 groups of 4 rows)
    const int wp  = parity ^ 1;

    const float* wih  = w_ih_all + (size_t)layer * 4 * Hd * Hd;
    const float* whh  = w_hh_all + (size_t)layer * 4 * Hd * Hd;
    const float* xsrc = &g_hbuf[wp][0][0][0];       // layer 1 input = layer 0 new h
    const float* hsrc = &g_hbuf[parity][layer][0][0];

    if (layer == 0 && tid < Bsz) toks[tid] = g_xt[tid];

    float acc[4][4];
#pragma unroll
    for (int r = 0; r < 4; r++)
#pragma unroll
        for (int g = 0; g < 4; g++) acc[r][g] = 0.0f;

    for (int pass = 0; pass < 2; pass++) {
        const float* wmat = pass ? whh : wih;
        for (int k0 = 0; k0 < Hd; k0 += BK) {
            __syncthreads();
            // load x tile (coalesced global, conflict-free smem stores)
            for (int idx = tid; idx < Bsz * BK; idx += 128) {
                int r = idx >> 6, kk = idx & (BK - 1);
                float v;
                if (pass == 0) {
                    if (layer == 0) v = emb[(size_t)toks[r] * Ed + k0 + kk];
                    else            v = xsrc[r * Hd + k0 + kk];
                } else {
                    v = hsrc[r * Hd + k0 + kk];
                }
                xs[kk][r] = v;
            }
            // load weight tile: col c -> n = gate*Hd + j0 + jl
            for (int idx = tid; idx < 32 * BK; idx += 128) {
                int c = idx >> 6, kk = idx & (BK - 1);
                int n = ((c >> 3) << 10) + j0 + (c & 7);
                ws[kk][c] = wmat[(size_t)n * Hd + k0 + kk];
            }
            __syncthreads();
#pragma unroll 8
            for (int kk = 0; kk < BK; kk++) {
                float x0 = xs[kk][(rg << 2) + 0];
                float x1 = xs[kk][(rg << 2) + 1];
                float x2 = xs[kk][(rg << 2) + 2];
                float x3 = xs[kk][(rg << 2) + 3];
                float w0 = ws[kk][cg];
                float w1 = ws[kk][8 + cg];
                float w2 = ws[kk][16 + cg];
                float w3 = ws[kk][24 + cg];
                acc[0][0] += x0 * w0; acc[0][1] += x0 * w1; acc[0][2] += x0 * w2; acc[0][3] += x0 * w3;
                acc[1][0] += x1 * w0; acc[1][1] += x1 * w1; acc[1][2] += x1 * w2; acc[1][3] += x1 * w3;
                acc[2][0] += x2 * w0; acc[2][1] += x2 * w1; acc[2][2] += x2 * w2; acc[2][3] += x2 * w3;
                acc[3][0] += x3 * w0; acc[3][1] += x3 * w1; acc[3][2] += x3 * w2; acc[3][3] += x3 * w3;
            }
        }
    }

    // epilogue: biases + cell update (gate order i, f, g, o)
    const int j = j0 + cg;
    const float bI = b_ih_all[layer * 4 * Hd + 0 * Hd + j] + b_hh_all[layer * 4 * Hd + 0 * Hd + j];
    const float bF = b_ih_all[layer * 4 * Hd + 1 * Hd + j] + b_hh_all[layer * 4 * Hd + 1 * Hd + j];
    const float bG = b_ih_all[layer * 4 * Hd + 2 * Hd + j] + b_hh_all[layer * 4 * Hd + 2 * Hd + j];
    const float bO = b_ih_all[layer * 4 * Hd + 3 * Hd + j] + b_hh_all[layer * 4 * Hd + 3 * Hd + j];

#pragma unroll
    for (int r = 0; r < 4; r++) {
        int row = (rg << 2) + r;
        float gi = acc[r][0] + bI;
        float gf = acc[r][1] + bF;
        float gg = acc[r][2] + bG;
        float go = acc[r][3] + bO;
        float cold = g_cbuf[layer][row][j];
        float cnew = sigmoidf_(gf) * cold + sigmoidf_(gi) * tanhf(gg);
        float hnew = sigmoidf_(go) * tanhf(cnew);
        g_cbuf[layer][row][j]      = cnew;
        g_hbuf[wp][layer][row][j]  = hnew;
    }
}

// ---------------- o2emb: hid = relu(h_top @ W^T + b) ----------------
// grid = 16 blocks (64 cols each), block = 256 threads, 4 rows x 4 cols per thread.
__global__ __launch_bounds__(256) void o2emb_kernel(
    const float* __restrict__ o2w, const float* __restrict__ o2b, int parity)
{
    __shared__ float xs[BK][Bsz + 1];
    __shared__ float ws[BK][64 + 1];

    const int tid = threadIdx.x;
    const int n0  = blockIdx.x * 64;
    const int cg  = tid & 15;    // 16 col groups, cols = cg + 16*cc
    const int rg  = tid >> 4;    // 16 row groups of 4
    const int wp  = parity ^ 1;
    const float* xsrc = &g_hbuf[wp][Ll - 1][0][0];

    float acc[4][4];
#pragma unroll
    for (int r = 0; r < 4; r++)
#pragma unroll
        for (int c = 0; c < 4; c++) acc[r][c] = 0.0f;

    for (int k0 = 0; k0 < Hd; k0 += BK) {
        __syncthreads();
        for (int idx = tid; idx < Bsz * BK; idx += 256) {
            int r = idx >> 6, kk = idx & (BK - 1);
            xs[kk][r] = xsrc[r * Hd + k0 + kk];
        }
        for (int idx = tid; idx < 64 * BK; idx += 256) {
            int c = idx >> 6, kk = idx & (BK - 1);
            ws[kk][c] = o2w[(size_t)(n0 + c) * Hd + k0 + kk];
        }
        __syncthreads();
#pragma unroll 8
        for (int kk = 0; kk < BK; kk++) {
            float x0 = xs[kk][(rg << 2) + 0];
            float x1 = xs[kk][(rg << 2) + 1];
            float x2 = xs[kk][(rg << 2) + 2];
            float x3 = xs[kk][(rg << 2) + 3];
#pragma unroll
            for (int c = 0; c < 4; c++) {
                float w = ws[kk][cg + 16 * c];
                acc[0][c] += x0 * w;
                acc[1][c] += x1 * w;
                acc[2][c] += x2 * w;
                acc[3][c] += x3 * w;
            }
        }
    }
#pragma unroll
    for (int r = 0; r < 4; r++) {
        int row = (rg << 2) + r;
#pragma unroll
        for (int c = 0; c < 4; c++) {
            int n = n0 + cg + 16 * c;
            float v = acc[r][c] + o2b[n];
            g_hid[row][n] = v > 0.0f ? v : 0.0f;
        }
    }
}

// ---------------- score: s = hid @ score_w^T + b, write scores, argmax partials ----------------
// grid = 250 blocks (128 cols each), block = 256 threads, 4 rows x 8 cols per thread.
__global__ __launch_bounds__(256) void score_kernel(
    const float* __restrict__ score_w, const float* __restrict__ score_b,
    float* __restrict__ out, int t, int out_size)
{
    __shared__ float xs[BK][Bsz + 1];
    __shared__ float ws[BK][SCORE_TN + 1];
    __shared__ float sval[Bsz][16];
    __shared__ int   sidx[Bsz][16];

    const int tid = threadIdx.x;
    const int n0  = blockIdx.x * SCORE_TN;
    const int cg  = tid & 15;    // cols = cg + 16*cc, cc in [0,8)
    const int rg  = tid >> 4;    // rows rg*4 .. rg*4+3

    float acc[4][8];
#pragma unroll
    for (int r = 0; r < 4; r++)
#pragma unroll
        for (int c = 0; c < 8; c++) acc[r][c] = 0.0f;

    for (int k0 = 0; k0 < Ed; k0 += BK) {
        __syncthreads();
        for (int idx = tid; idx < Bsz * BK; idx += 256) {
            int r = idx >> 6, kk = idx & (BK - 1);
            xs[kk][r] = g_hid[r][k0 + kk];
        }
        for (int idx = tid; idx < SCORE_TN * BK; idx += 256) {
            int c = idx >> 6, kk = idx & (BK - 1);
            ws[kk][c] = score_w[(size_t)(n0 + c) * Ed + k0 + kk];
        }
        __syncthreads();
#pragma unroll 8
        for (int kk = 0; kk < BK; kk++) {
            float x0 = xs[kk][(rg << 2) + 0];
            float x1 = xs[kk][(rg << 2) + 1];
            float x2 = xs[kk][(rg << 2) + 2];
            float x3 = xs[kk][(rg << 2) + 3];
#pragma unroll
            for (int c = 0; c < 8; c++) {
                float w = ws[kk][cg + 16 * c];
                acc[0][c] += x0 * w;
                acc[1][c] += x1 * w;
                acc[2][c] += x2 * w;
                acc[3][c] += x3 * w;
            }
        }
    }

    // epilogue: bias, write scores [b][t][v], per-thread-row best (ties: lowest idx)
    const long long lim  = out_size;
    const long long tOff = (long long)t * Vv;
#pragma unroll
    for (int r = 0; r < 4; r++) {
        int row = (rg << 2) + r;
        long long rowBase = (long long)row * Tt * Vv + tOff;
        float bb = -3.4e38f;
        int   bi = 0x7fffffff;
#pragma unroll
        for (int c = 0; c < 8; c++) {
            int n = n0 + cg + 16 * c;
            float s = acc[r][c] + score_b[n];
            long long off = rowBase + n;
            if (off < lim) out[off] = s;
            if (s > bb || (s == bb && n < bi)) { bb = s; bi = n; }
        }
        sval[row][cg] = bb;
        sidx[row][cg] = bi;
    }
    __syncthreads();
    if (tid < Bsz) {
        int row = tid;
        float bb = sval[row][0];
        int   bi = sidx[row][0];
#pragma unroll
        for (int g = 1; g < 16; g++) {
            float v = sval[row][g];
            int   i = sidx[row][g];
            if (v > bb || (v == bb && i < bi)) { bb = v; bi = i; }
        }
        g_pval[row][blockIdx.x] = bb;
        g_pidx[row][blockIdx.x] = bi;
    }
}

// ---------------- argmax reduce: partials -> next token + samples output ----------------
__global__ __launch_bounds__(128) void argmax_kernel(float* __restrict__ out, int t, int out_size) {
    __shared__ float sv[128];
    __shared__ int   si[128];
    const int row = blockIdx.x;
    const int tid = threadIdx.x;

    float bv = -3.4e38f;
    int   bi = 0x7fffffff;
    for (int p = tid; p < NBLK_SCORE; p += 128) {
        float v = g_pval[row][p];
        int   i = g_pidx[row][p];
        if (v > bv || (v == bv && i < bi)) { bv = v; bi = i; }
    }
    sv[tid] = bv; si[tid] = bi;
    __syncthreads();
    for (int s = 64; s > 0; s >>= 1) {
        if (tid < s) {
            float v = sv[tid + s];
            int   i = si[tid + s];
            if (v > sv[tid] || (v == sv[tid] && i < si[tid])) { sv[tid] = v; si[tid] = i; }
        }
        __syncthreads();
    }
    if (tid == 0) {
        g_xt[row] = si[0];
        long long off = (long long)Bsz * Tt * Vv + (long long)row * Tt + t;
        if (off < (long long)out_size) out[off] = (float)si[0];
    }
}

// ---------------- launch ----------------
extern "C" void kernel_launch(void* const* d_in, const int* in_sizes, int n_in,
                              void* d_out, int out_size) {
    const float* emb   = (const float*)d_in[0];
    const float* w_ih  = (const float*)d_in[1];
    const float* w_hh  = (const float*)d_in[2];
    const float* b_ih  = (const float*)d_in[3];
    const float* b_hh  = (const float*)d_in[4];
    const float* o2w   = (const float*)d_in[5];
    const float* o2b   = (const float*)d_in[6];
    const float* sw    = (const float*)d_in[7];
    const float* sb    = (const float*)d_in[8];
    float* out = (float*)d_out;
    (void)in_sizes; (void)n_in;

    init_kernel<<<512, 256>>>();
    for (int t = 0; t < Tt; t++) {
        int parity = t & 1;
        lstm_kernel<<<128, 128>>>(emb, w_ih, w_hh, b_ih, b_hh, 0, parity);
        lstm_kernel<<<128, 128>>>(emb, w_ih, w_hh, b_ih, b_hh, 1, parity);
        o2emb_kernel<<<16, 256>>>(o2w, o2b, parity);
        score_kernel<<<NBLK_SCORE, 256>>>(sw, sb, out, t, out_size);
        argmax_kernel<<<Bsz, 128>>>(out, t, out_size);
    }
}

// round 4
// speedup vs baseline: 2.5490x; 2.5490x over previous
#include <cuda_runtime.h>
#include <math.h>

#define Bsz 64
#define Hd  1024
#define Ed  1024
#define Vv  32000
#define Ll  2
#define Tt  64
#define START_TOK 1

#define BK 32                       // K-chunk
#define XPAD 34                     // smem row stride in floats (8B-aligned, conflict-free)
#define SCORE_TN 128
#define NBLK_SCORE (Vv / SCORE_TN)  // 250

typedef unsigned long long ull;

// ---------------- persistent device state ----------------
__device__ float g_hbuf[2][Ll][Bsz][Hd];
__device__ float g_cbuf[Ll][Bsz][Hd];
__device__ int   g_xt[Bsz];
__device__ float g_hid[Bsz][Ed];
__device__ float g_pval[Bsz][NBLK_SCORE];
__device__ int   g_pidx[Bsz][NBLK_SCORE];

// packed fp32x2 FMA: acc.lo += a.lo*b.lo ; acc.hi += a.hi*b.hi
__device__ __forceinline__ void ffma2(ull &acc, ull a, ull b) {
    asm("fma.rn.f32x2 %0, %1, %2, %0;" : "+l"(acc) : "l"(a), "l"(b));
}
__device__ __forceinline__ float fsum2(ull v) {
    return __uint_as_float((unsigned)v) + __uint_as_float((unsigned)(v >> 32));
}
__device__ __forceinline__ float sigmoidf_(float x) { return 1.0f / (1.0f + expf(-x)); }

// ---------------- init ----------------
__global__ void init_kernel() {
    int idx = blockIdx.x * blockDim.x + threadIdx.x;
    float* c = &g_cbuf[0][0][0];
    float* h = &g_hbuf[0][0][0][0];
    if (idx < Ll * Bsz * Hd) { c[idx] = 0.0f; h[idx] = 0.0f; }
    if (idx < Bsz) g_xt[idx] = START_TOK;
}

// ---------------- fused LSTM layer ----------------
// grid = 128 blocks (8 j each, 32 smem cols = 4 gates x 8 j), 256 threads.
// Thread tile: 2 rows x 4 gates of one j. K loop: 64 chunks (w_ih K=1024 then w_hh K=1024).
__global__ __launch_bounds__(256) void lstm_kernel(
    const float* __restrict__ emb,
    const float* __restrict__ w_ih_all, const float* __restrict__ w_hh_all,
    const float* __restrict__ b_ih_all, const float* __restrict__ b_hh_all,
    int layer, int parity)
{
    __shared__ float xs[Bsz][XPAD];
    __shared__ float ws[32][XPAD];

    const int tid = threadIdx.x;
    const int j0  = blockIdx.x * 8;
    const int cg  = tid & 7;      // j within tile
    const int rg  = tid >> 3;     // 0..31, rows 2*rg, 2*rg+1
    const int wp  = parity ^ 1;

    const float* wih = w_ih_all + (size_t)layer * 4 * Hd * Hd;
    const float* whh = w_hh_all + (size_t)layer * 4 * Hd * Hd;

    // x source pointer for chunk (64 chunks: 0..31 -> w_ih input x, 32..63 -> w_hh input h)
    auto xrow = [&](int chunk, int r) -> const float* {
        int k0 = (chunk & 31) * BK;
        if (chunk < 32) {
            if (layer == 0) return &emb[(size_t)g_xt[r] * Ed + k0];
            return &g_hbuf[wp][0][r][k0];
        }
        return &g_hbuf[parity][layer][r][k0];
    };

    ull acc[2][4];
#pragma unroll
    for (int i = 0; i < 2; i++)
#pragma unroll
        for (int g = 0; g < 4; g++) acc[i][g] = 0ULL;

    // prefetch regs: x 2 float4, w 1 float4
    float4 px[2], pw;
    {
        // chunk 0
#pragma unroll
        for (int i = 0; i < 2; i++) {
            int item = tid + 256 * i;          // 512 float4 items
            int r = item >> 3, c4 = item & 7;
            px[i] = *(const float4*)(xrow(0, r) + 4 * c4);
        }
        int c = tid >> 3, c4 = tid & 7;        // 256 float4 items
        int n = ((c >> 3) << 10) + j0 + (c & 7);
        pw = *(const float4*)&wih[(size_t)n * Hd + 0 * BK + 4 * c4];
    }

    for (int chunk = 0; chunk < 64; chunk++) {
        // store prefetched tile
#pragma unroll
        for (int i = 0; i < 2; i++) {
            int item = tid + 256 * i;
            int r = item >> 3, c4 = item & 7;
            xs[r][4 * c4 + 0] = px[i].x;
            xs[r][4 * c4 + 1] = px[i].y;
            xs[r][4 * c4 + 2] = px[i].z;
            xs[r][4 * c4 + 3] = px[i].w;
        }
        {
            int c = tid >> 3, c4 = tid & 7;
            ws[c][4 * c4 + 0] = pw.x;
            ws[c][4 * c4 + 1] = pw.y;
            ws[c][4 * c4 + 2] = pw.z;
            ws[c][4 * c4 + 3] = pw.w;
        }
        __syncthreads();

        // prefetch next chunk (overlaps with compute below)
        if (chunk + 1 < 64) {
            int nc = chunk + 1;
#pragma unroll
            for (int i = 0; i < 2; i++) {
                int item = tid + 256 * i;
                int r = item >> 3, c4 = item & 7;
                px[i] = *(const float4*)(xrow(nc, r) + 4 * c4);
            }
            int c = tid >> 3, c4 = tid & 7;
            int n = ((c >> 3) << 10) + j0 + (c & 7);
            const float* wmat = (nc < 32) ? wih : whh;
            int k0 = (nc & 31) * BK;
            pw = *(const float4*)&wmat[(size_t)n * Hd + k0 + 4 * c4];
        }

        // compute: packed over K pairs
#pragma unroll
        for (int k2 = 0; k2 < BK / 2; k2++) {
            ull xv0 = *(const ull*)&xs[2 * rg + 0][2 * k2];
            ull xv1 = *(const ull*)&xs[2 * rg + 1][2 * k2];
#pragma unroll
            for (int g = 0; g < 4; g++) {
                ull wv = *(const ull*)&ws[g * 8 + cg][2 * k2];
                ffma2(acc[0][g], xv0, wv);
                ffma2(acc[1][g], xv1, wv);
            }
        }
        __syncthreads();
    }

    // epilogue: biases + cell update (gate order i,f,g,o)
    const int j = j0 + cg;
    const float bI = b_ih_all[layer * 4 * Hd + 0 * Hd + j] + b_hh_all[layer * 4 * Hd + 0 * Hd + j];
    const float bF = b_ih_all[layer * 4 * Hd + 1 * Hd + j] + b_hh_all[layer * 4 * Hd + 1 * Hd + j];
    const float bG = b_ih_all[layer * 4 * Hd + 2 * Hd + j] + b_hh_all[layer * 4 * Hd + 2 * Hd + j];
    const float bO = b_ih_all[layer * 4 * Hd + 3 * Hd + j] + b_hh_all[layer * 4 * Hd + 3 * Hd + j];

#pragma unroll
    for (int i = 0; i < 2; i++) {
        int row = 2 * rg + i;
        float gi = fsum2(acc[i][0]) + bI;
        float gf = fsum2(acc[i][1]) + bF;
        float gg = fsum2(acc[i][2]) + bG;
        float go = fsum2(acc[i][3]) + bO;
        float cold = g_cbuf[layer][row][j];
        float cnew = sigmoidf_(gf) * cold + sigmoidf_(gi) * tanhf(gg);
        float hnew = sigmoidf_(go) * tanhf(cnew);
        g_cbuf[layer][row][j]     = cnew;
        g_hbuf[wp][layer][row][j] = hnew;
    }
}

// ---------------- o2emb: hid = relu(h_top @ W^T + b) ----------------
// grid = 128 blocks (8 cols each), 128 threads, thread tile 4 rows x 1 col.
__global__ __launch_bounds__(128) void o2emb_kernel(
    const float* __restrict__ o2w, const float* __restrict__ o2b, int parity)
{
    __shared__ float xs[Bsz][XPAD];
    __shared__ float ws[8][XPAD];

    const int tid = threadIdx.x;
    const int n0  = blockIdx.x * 8;
    const int cg  = tid & 7;
    const int rg  = tid >> 3;    // 0..15, rows 4*rg..+3
    const int wp  = parity ^ 1;
    const float* xsrc = &g_hbuf[wp][Ll - 1][0][0];

    ull acc[4];
#pragma unroll
    for (int i = 0; i < 4; i++) acc[i] = 0ULL;

    float4 px[4], pw;
    {
#pragma unroll
        for (int i = 0; i < 4; i++) {
            int item = tid + 128 * i;
            int r = item >> 3, c4 = item & 7;
            px[i] = *(const float4*)&xsrc[r * Hd + 4 * c4];
        }
        if (tid < 64) {
            int c = tid >> 3, c4 = tid & 7;
            pw = *(const float4*)&o2w[(size_t)(n0 + c) * Hd + 4 * c4];
        }
    }

    const int NCH = Hd / BK;  // 32
    for (int chunk = 0; chunk < NCH; chunk++) {
#pragma unroll
        for (int i = 0; i < 4; i++) {
            int item = tid + 128 * i;
            int r = item >> 3, c4 = item & 7;
            xs[r][4 * c4 + 0] = px[i].x;
            xs[r][4 * c4 + 1] = px[i].y;
            xs[r][4 * c4 + 2] = px[i].z;
            xs[r][4 * c4 + 3] = px[i].w;
        }
        if (tid < 64) {
            int c = tid >> 3, c4 = tid & 7;
            ws[c][4 * c4 + 0] = pw.x;
            ws[c][4 * c4 + 1] = pw.y;
            ws[c][4 * c4 + 2] = pw.z;
            ws[c][4 * c4 + 3] = pw.w;
        }
        __syncthreads();

        if (chunk + 1 < NCH) {
            int k0 = (chunk + 1) * BK;
#pragma unroll
            for (int i = 0; i < 4; i++) {
                int item = tid + 128 * i;
                int r = item >> 3, c4 = item & 7;
                px[i] = *(const float4*)&xsrc[r * Hd + k0 + 4 * c4];
            }
            if (tid < 64) {
                int c = tid >> 3, c4 = tid & 7;
                pw = *(const float4*)&o2w[(size_t)(n0 + c) * Hd + k0 + 4 * c4];
            }
        }

#pragma unroll
        for (int k2 = 0; k2 < BK / 2; k2++) {
            ull wv = *(const ull*)&ws[cg][2 * k2];
#pragma unroll
            for (int i = 0; i < 4; i++) {
                ull xv = *(const ull*)&xs[4 * rg + i][2 * k2];
                ffma2(acc[i], xv, wv);
            }
        }
        __syncthreads();
    }

    const int n = n0 + cg;
    const float b = o2b[n];
#pragma unroll
    for (int i = 0; i < 4; i++) {
        float v = fsum2(acc[i]) + b;
        g_hid[4 * rg + i][n] = v > 0.0f ? v : 0.0f;
    }
}

// ---------------- score GEMM + argmax partials ----------------
// grid = 250 blocks (128 cols), 256 threads, thread tile 4 rows x 8 cols.
__global__ __launch_bounds__(256) void score_kernel(
    const float* __restrict__ score_w, const float* __restrict__ score_b,
    float* __restrict__ out, int t, int out_size)
{
    __shared__ float xs[Bsz][XPAD];
    __shared__ float ws[SCORE_TN][XPAD];
    __shared__ float sval[Bsz][16];
    __shared__ int   sidx[Bsz][16];

    const int tid = threadIdx.x;
    const int n0  = blockIdx.x * SCORE_TN;
    const int cg  = tid & 15;    // cols = cg + 16*cc
    const int rg  = tid >> 4;    // 0..15, rows 4*rg..+3

    ull acc[4][8];
#pragma unroll
    for (int r = 0; r < 4; r++)
#pragma unroll
        for (int c = 0; c < 8; c++) acc[r][c] = 0ULL;

    float4 px[2], pw[4];
    {
#pragma unroll
        for (int i = 0; i < 2; i++) {
            int item = tid + 256 * i;
            int r = item >> 3, c4 = item & 7;
            px[i] = *(const float4*)&g_hid[r][4 * c4];
        }
#pragma unroll
        for (int i = 0; i < 4; i++) {
            int item = tid + 256 * i;
            int c = item >> 3, c4 = item & 7;
            pw[i] = *(const float4*)&score_w[(size_t)(n0 + c) * Ed + 4 * c4];
        }
    }

    const int NCH = Ed / BK;  // 32
    for (int chunk = 0; chunk < NCH; chunk++) {
#pragma unroll
        for (int i = 0; i < 2; i++) {
            int item = tid + 256 * i;
            int r = item >> 3, c4 = item & 7;
            xs[r][4 * c4 + 0] = px[i].x;
            xs[r][4 * c4 + 1] = px[i].y;
            xs[r][4 * c4 + 2] = px[i].z;
            xs[r][4 * c4 + 3] = px[i].w;
        }
#pragma unroll
        for (int i = 0; i < 4; i++) {
            int item = tid + 256 * i;
            int c = item >> 3, c4 = item & 7;
            ws[c][4 * c4 + 0] = pw[i].x;
            ws[c][4 * c4 + 1] = pw[i].y;
            ws[c][4 * c4 + 2] = pw[i].z;
            ws[c][4 * c4 + 3] = pw[i].w;
        }
        __syncthreads();

        if (chunk + 1 < NCH) {
            int k0 = (chunk + 1) * BK;
#pragma unroll
            for (int i = 0; i < 2; i++) {
                int item = tid + 256 * i;
                int r = item >> 3, c4 = item & 7;
                px[i] = *(const float4*)&g_hid[r][k0 + 4 * c4];
            }
#pragma unroll
            for (int i = 0; i < 4; i++) {
                int item = tid + 256 * i;
                int c = item >> 3, c4 = item & 7;
                pw[i] = *(const float4*)&score_w[(size_t)(n0 + c) * Ed + k0 + 4 * c4];
            }
        }

#pragma unroll
        for (int k2 = 0; k2 < BK / 2; k2++) {
            ull xv0 = *(const ull*)&xs[4 * rg + 0][2 * k2];
            ull xv1 = *(const ull*)&xs[4 * rg + 1][2 * k2];
            ull xv2 = *(const ull*)&xs[4 * rg + 2][2 * k2];
            ull xv3 = *(const ull*)&xs[4 * rg + 3][2 * k2];
#pragma unroll
            for (int cc = 0; cc < 8; cc++) {
                ull wv = *(const ull*)&ws[cg + 16 * cc][2 * k2];
                ffma2(acc[0][cc], xv0, wv);
                ffma2(acc[1][cc], xv1, wv);
                ffma2(acc[2][cc], xv2, wv);
                ffma2(acc[3][cc], xv3, wv);
            }
        }
        __syncthreads();
    }

    // epilogue: bias, scores write, per-thread argmax partial (ties -> lowest idx)
    const long long lim  = out_size;
    const long long tOff = (long long)t * Vv;
#pragma unroll
    for (int r = 0; r < 4; r++) {
        int row = 4 * rg + r;
        long long rowBase = (long long)row * Tt * Vv + tOff;
        float bb = -3.4e38f;
        int   bi = 0x7fffffff;
#pragma unroll
        for (int cc = 0; cc < 8; cc++) {
            int n = n0 + cg + 16 * cc;
            float s = fsum2(acc[r][cc]) + score_b[n];
            long long off = rowBase + n;
            if (off < lim) out[off] = s;
            if (s > bb || (s == bb && n < bi)) { bb = s; bi = n; }
        }
        sval[row][cg] = bb;
        sidx[row][cg] = bi;
    }
    __syncthreads();
    if (tid < Bsz) {
        int row = tid;
        float bb = sval[row][0];
        int   bi = sidx[row][0];
#pragma unroll
        for (int g = 1; g < 16; g++) {
            float v = sval[row][g];
            int   i = sidx[row][g];
            if (v > bb || (v == bb && i < bi)) { bb = v; bi = i; }
        }
        g_pval[row][blockIdx.x] = bb;
        g_pidx[row][blockIdx.x] = bi;
    }
}

// ---------------- argmax reduce -> next token + samples ----------------
__global__ __launch_bounds__(128) void argmax_kernel(float* __restrict__ out, int t, int out_size) {
    __shared__ float sv[128];
    __shared__ int   si[128];
    const int row = blockIdx.x;
    const int tid = threadIdx.x;

    float bv = -3.4e38f;
    int   bi = 0x7fffffff;
    for (int p = tid; p < NBLK_SCORE; p += 128) {
        float v = g_pval[row][p];
        int   i = g_pidx[row][p];
        if (v > bv || (v == bv && i < bi)) { bv = v; bi = i; }
    }
    sv[tid] = bv; si[tid] = bi;
    __syncthreads();
    for (int s = 64; s > 0; s >>= 1) {
        if (tid < s) {
            float v = sv[tid + s];
            int   i = si[tid + s];
            if (v > sv[tid] || (v == sv[tid] && i < si[tid])) { sv[tid] = v; si[tid] = i; }
        }
        __syncthreads();
    }
    if (tid == 0) {
        g_xt[row] = si[0];
        long long off = (long long)Bsz * Tt * Vv + (long long)row * Tt + t;
        if (off < (long long)out_size) out[off] = (float)si[0];
    }
}

// ---------------- launch ----------------
extern "C" void kernel_launch(void* const* d_in, const int* in_sizes, int n_in,
                              void* d_out, int out_size) {
    const float* emb   = (const float*)d_in[0];
    const float* w_ih  = (const float*)d_in[1];
    const float* w_hh  = (const float*)d_in[2];
    const float* b_ih  = (const float*)d_in[3];
    const float* b_hh  = (const float*)d_in[4];
    const float* o2w   = (const float*)d_in[5];
    const float* o2b   = (const float*)d_in[6];
    const float* sw    = (const float*)d_in[7];
    const float* sb    = (const float*)d_in[8];
    float* out = (float*)d_out;
    (void)in_sizes; (void)n_in;

    init_kernel<<<512, 256>>>();
    for (int t = 0; t < Tt; t++) {
        int parity = t & 1;
        lstm_kernel<<<128, 256>>>(emb, w_ih, w_hh, b_ih, b_hh, 0, parity);
        lstm_kernel<<<128, 256>>>(emb, w_ih, w_hh, b_ih, b_hh, 1, parity);
        o2emb_kernel<<<128, 128>>>(o2w, o2b, parity);
        score_kernel<<<NBLK_SCORE, 256>>>(sw, sb, out, t, out_size);
        argmax_kernel<<<Bsz, 128>>>(out, t, out_size);
    }
}

// round 9
// speedup vs baseline: 2.9762x; 1.1676x over previous
#include <cuda_runtime.h>
#include <cuda_bf16.h>
#include <math.h>
#include <stdint.h>

#define Bsz 64
#define Hd  1024
#define Ed  1024
#define Vv  32000
#define Ll  2
#define Tt  64
#define START_TOK 1

#define BK 32
#define XPAD 34
#define VT 128                        // vocab rows per score tile
#define NBLK_SCORE (Vv / VT)          // 250
#define KC 64                         // bf16 K elems per chunk (128B rows)
#define NCH (Hd / KC)                 // 16 chunks
#define A_PART 16384                  // 128 rows * 128B
#define B_PART 8192                   // 64 rows * 128B
#define A_REGION (3 * A_PART)         // 49152
#define STAGE_BYTES (A_REGION + 3 * B_PART)  // 73728
#define N_STAGES 3
#define DYN_BYTES (N_STAGES * STAGE_BYTES + 1024)

typedef unsigned long long ull;

// ---------------- persistent device state ----------------
__device__ float g_hbuf[2][Ll][Bsz][Hd];
__device__ float g_cbuf[Ll][Bsz][Hd];
__device__ int   g_xt[Bsz];
__device__ float g_pval[Bsz][NBLK_SCORE];
__device__ int   g_pidx[Bsz][NBLK_SCORE];

// bf16 3-way splits (scratch; __device__ globals are the allowed scratch)
__device__ __nv_bfloat16 g_w0[(size_t)Vv * Ed];
__device__ __nv_bfloat16 g_w1[(size_t)Vv * Ed];
__device__ __nv_bfloat16 g_w2[(size_t)Vv * Ed];
__device__ __nv_bfloat16 g_h0[Bsz * Ed];
__device__ __nv_bfloat16 g_h1[Bsz * Ed];
__device__ __nv_bfloat16 g_h2[Bsz * Ed];

// ---------------- helpers ----------------
__device__ __forceinline__ void ffma2(ull &acc, ull a, ull b) {
    asm("fma.rn.f32x2 %0, %1, %2, %0;" : "+l"(acc) : "l"(a), "l"(b));
}
__device__ __forceinline__ float fsum2(ull v) {
    return __uint_as_float((unsigned)v) + __uint_as_float((unsigned)(v >> 32));
}
__device__ __forceinline__ float sigmoidf_(float x) { return 1.0f / (1.0f + expf(-x)); }

__device__ __forceinline__ uint32_t smem_u32(const void* p) {
    uint32_t a;
    asm("{ .reg .u64 t; cvta.to.shared.u64 t, %1; cvt.u32.u64 %0, t; }" : "=r"(a) : "l"(p));
    return a;
}
__device__ __forceinline__ void cpa16(uint32_t dst, const void* src) {
    asm volatile("cp.async.cg.shared.global [%0], [%1], 16;" :: "r"(dst), "l"(src) : "memory");
}
__device__ __forceinline__ void cpa_commit() {
    asm volatile("cp.async.commit_group;" ::: "memory");
}
template <int N> __device__ __forceinline__ void cpa_wait() {
    asm volatile("cp.async.wait_group %0;" :: "n"(N) : "memory");
}

// ldmatrix: 4x (8x8 b16) tiles; lanes 0-7/8-15/16-23/24-31 address tiles 0..3
__device__ __forceinline__ void ldsm_x4(uint32_t* r, uint32_t addr) {
    asm volatile("ldmatrix.sync.aligned.m8n8.x4.shared.b16 {%0,%1,%2,%3}, [%4];"
                 : "=r"(r[0]), "=r"(r[1]), "=r"(r[2]), "=r"(r[3]) : "r"(addr));
}
// mma m16n8k16 bf16 -> fp32 accumulate
__device__ __forceinline__ void mma_bf16(float* d, const uint32_t* a, uint32_t b0, uint32_t b1) {
    asm volatile(
        "mma.sync.aligned.m16n8k16.row.col.f32.bf16.bf16.f32 "
        "{%0,%1,%2,%3}, {%4,%5,%6,%7}, {%8,%9}, {%0,%1,%2,%3};"
        : "+f"(d[0]), "+f"(d[1]), "+f"(d[2]), "+f"(d[3])
        : "r"(a[0]), "r"(a[1]), "r"(a[2]), "r"(a[3]), "r"(b0), "r"(b1));
}
__device__ __forceinline__ uint32_t swz(uint32_t off) { return off ^ ((off >> 3) & 0x70); }

// ---------------- init ----------------
__global__ void init_kernel() {
    int idx = blockIdx.x * blockDim.x + threadIdx.x;
    float* c = &g_cbuf[0][0][0];
    float* h = &g_hbuf[0][0][0][0];
    if (idx < Ll * Bsz * Hd) { c[idx] = 0.0f; h[idx] = 0.0f; }
    if (idx < Bsz) g_xt[idx] = START_TOK;
}

// ---------------- weight split (once per launch) ----------------
__global__ __launch_bounds__(256) void split_w_kernel(const float* __restrict__ sw) {
    const size_t n = (size_t)Vv * Ed;
    for (size_t i = blockIdx.x * 256ull + threadIdx.x; i < n; i += (size_t)gridDim.x * 256ull) {
        float w = sw[i];
        __nv_bfloat16 a = __float2bfloat16(w);
        float r1 = w - __bfloat162float(a);
        __nv_bfloat16 b = __float2bfloat16(r1);
        float r2 = r1 - __bfloat162float(b);
        g_w0[i] = a; g_w1[i] = b; g_w2[i] = __float2bfloat16(r2);
    }
}

// ---------------- fused LSTM layer (scalar FFMA2) ----------------
__global__ __launch_bounds__(256) void lstm_kernel(
    const float* __restrict__ emb,
    const float* __restrict__ w_ih_all, const float* __restrict__ w_hh_all,
    const float* __restrict__ b_ih_all, const float* __restrict__ b_hh_all,
    int layer, int parity)
{
    __shared__ float xs[Bsz][XPAD];
    __shared__ float ws[32][XPAD];

    const int tid = threadIdx.x;
    const int j0  = blockIdx.x * 8;
    const int cg  = tid & 7;
    const int rg  = tid >> 3;
    const int wp  = parity ^ 1;

    const float* wih = w_ih_all + (size_t)layer * 4 * Hd * Hd;
    const float* whh = w_hh_all + (size_t)layer * 4 * Hd * Hd;

    auto xrow = [&](int chunk, int r) -> const float* {
        int k0 = (chunk & 31) * BK;
        if (chunk < 32) {
            if (layer == 0) return &emb[(size_t)g_xt[r] * Ed + k0];
            return &g_hbuf[wp][0][r][k0];
        }
        return &g_hbuf[parity][layer][r][k0];
    };

    ull acc[2][4];
#pragma unroll
    for (int i = 0; i < 2; i++)
#pragma unroll
        for (int g = 0; g < 4; g++) acc[i][g] = 0ULL;

    float4 px[2], pw;
    {
#pragma unroll
        for (int i = 0; i < 2; i++) {
            int item = tid + 256 * i;
            int r = item >> 3, c4 = item & 7;
            px[i] = *(const float4*)(xrow(0, r) + 4 * c4);
        }
        int c = tid >> 3, c4 = tid & 7;
        int n = ((c >> 3) << 10) + j0 + (c & 7);
        pw = *(const float4*)&wih[(size_t)n * Hd + 4 * c4];
    }

    for (int chunk = 0; chunk < 64; chunk++) {
#pragma unroll
        for (int i = 0; i < 2; i++) {
            int item = tid + 256 * i;
            int r = item >> 3, c4 = item & 7;
            xs[r][4 * c4 + 0] = px[i].x; xs[r][4 * c4 + 1] = px[i].y;
            xs[r][4 * c4 + 2] = px[i].z; xs[r][4 * c4 + 3] = px[i].w;
        }
        {
            int c = tid >> 3, c4 = tid & 7;
            ws[c][4 * c4 + 0] = pw.x; ws[c][4 * c4 + 1] = pw.y;
            ws[c][4 * c4 + 2] = pw.z; ws[c][4 * c4 + 3] = pw.w;
        }
        __syncthreads();

        if (chunk + 1 < 64) {
            int nc = chunk + 1;
#pragma unroll
            for (int i = 0; i < 2; i++) {
                int item = tid + 256 * i;
                int r = item >> 3, c4 = item & 7;
                px[i] = *(const float4*)(xrow(nc, r) + 4 * c4);
            }
            int c = tid >> 3, c4 = tid & 7;
            int n = ((c >> 3) << 10) + j0 + (c & 7);
            const float* wmat = (nc < 32) ? wih : whh;
            int k0 = (nc & 31) * BK;
            pw = *(const float4*)&wmat[(size_t)n * Hd + k0 + 4 * c4];
        }

#pragma unroll
        for (int k2 = 0; k2 < BK / 2; k2++) {
            ull xv0 = *(const ull*)&xs[2 * rg + 0][2 * k2];
            ull xv1 = *(const ull*)&xs[2 * rg + 1][2 * k2];
#pragma unroll
            for (int g = 0; g < 4; g++) {
                ull wv = *(const ull*)&ws[g * 8 + cg][2 * k2];
                ffma2(acc[0][g], xv0, wv);
                ffma2(acc[1][g], xv1, wv);
            }
        }
        __syncthreads();
    }

    const int j = j0 + cg;
    const float bI = b_ih_all[layer * 4 * Hd + 0 * Hd + j] + b_hh_all[layer * 4 * Hd + 0 * Hd + j];
    const float bF = b_ih_all[layer * 4 * Hd + 1 * Hd + j] + b_hh_all[layer * 4 * Hd + 1 * Hd + j];
    const float bG = b_ih_all[layer * 4 * Hd + 2 * Hd + j] + b_hh_all[layer * 4 * Hd + 2 * Hd + j];
    const float bO = b_ih_all[layer * 4 * Hd + 3 * Hd + j] + b_hh_all[layer * 4 * Hd + 3 * Hd + j];

#pragma unroll
    for (int i = 0; i < 2; i++) {
        int row = 2 * rg + i;
        float gi = fsum2(acc[i][0]) + bI;
        float gf = fsum2(acc[i][1]) + bF;
        float gg = fsum2(acc[i][2]) + bG;
        float go = fsum2(acc[i][3]) + bO;
        float cold = g_cbuf[layer][row][j];
        float cnew = sigmoidf_(gf) * cold + sigmoidf_(gi) * tanhf(gg);
        float hnew = sigmoidf_(go) * tanhf(cnew);
        g_cbuf[layer][row][j]     = cnew;
        g_hbuf[wp][layer][row][j] = hnew;
    }
}

// ---------------- o2emb: hid = relu(h_top @ W^T + b) -> bf16 3-way split ----------------
__global__ __launch_bounds__(128) void o2emb_kernel(
    const float* __restrict__ o2w, const float* __restrict__ o2b, int parity)
{
    __shared__ float xs[Bsz][XPAD];
    __shared__ float ws[8][XPAD];

    const int tid = threadIdx.x;
    const int n0  = blockIdx.x * 8;
    const int cg  = tid & 7;
    const int rg  = tid >> 3;
    const int wp  = parity ^ 1;
    const float* xsrc = &g_hbuf[wp][Ll - 1][0][0];

    ull acc[4];
#pragma unroll
    for (int i = 0; i < 4; i++) acc[i] = 0ULL;

    float4 px[4], pw;
    {
#pragma unroll
        for (int i = 0; i < 4; i++) {
            int item = tid + 128 * i;
            int r = item >> 3, c4 = item & 7;
            px[i] = *(const float4*)&xsrc[r * Hd + 4 * c4];
        }
        if (tid < 64) {
            int c = tid >> 3, c4 = tid & 7;
            pw = *(const float4*)&o2w[(size_t)(n0 + c) * Hd + 4 * c4];
        }
    }

    const int NCHU = Hd / BK;
    for (int chunk = 0; chunk < NCHU; chunk++) {
#pragma unroll
        for (int i = 0; i < 4; i++) {
            int item = tid + 128 * i;
            int r = item >> 3, c4 = item & 7;
            xs[r][4 * c4 + 0] = px[i].x; xs[r][4 * c4 + 1] = px[i].y;
            xs[r][4 * c4 + 2] = px[i].z; xs[r][4 * c4 + 3] = px[i].w;
        }
        if (tid < 64) {
            int c = tid >> 3, c4 = tid & 7;
            ws[c][4 * c4 + 0] = pw.x; ws[c][4 * c4 + 1] = pw.y;
            ws[c][4 * c4 + 2] = pw.z; ws[c][4 * c4 + 3] = pw.w;
        }
        __syncthreads();

        if (chunk + 1 < NCHU) {
            int k0 = (chunk + 1) * BK;
#pragma unroll
            for (int i = 0; i < 4; i++) {
                int item = tid + 128 * i;
                int r = item >> 3, c4 = item & 7;
                px[i] = *(const float4*)&xsrc[r * Hd + k0 + 4 * c4];
            }
            if (tid < 64) {
                int c = tid >> 3, c4 = tid & 7;
                pw = *(const float4*)&o2w[(size_t)(n0 + c) * Hd + k0 + 4 * c4];
            }
        }

#pragma unroll
        for (int k2 = 0; k2 < BK / 2; k2++) {
            ull wv = *(const ull*)&ws[cg][2 * k2];
#pragma unroll
            for (int i = 0; i < 4; i++) {
                ull xv = *(const ull*)&xs[4 * rg + i][2 * k2];
                ffma2(acc[i], xv, wv);
            }
        }
        __syncthreads();
    }

    const int n = n0 + cg;
    const float b = o2b[n];
#pragma unroll
    for (int i = 0; i < 4; i++) {
        float v = fsum2(acc[i]) + b;
        v = v > 0.0f ? v : 0.0f;
        __nv_bfloat16 p0 = __float2bfloat16(v);
        float r1 = v - __bfloat162float(p0);
        __nv_bfloat16 p1 = __float2bfloat16(r1);
        float r2 = r1 - __bfloat162float(p1);
        int idx = (4 * rg + i) * Ed + n;
        g_h0[idx] = p0; g_h1[idx] = p1; g_h2[idx] = __float2bfloat16(r2);
    }
}

// ---------------- score via mma.sync bf16x3: D[v,b] = W'[v,:] . h'[b,:] ----------------
// 250 CTAs x 256 threads (8 warps). Warp w owns vocab rows [16w,16w+16), all 64 batch cols.
// 6 cross products (w0h0,w0h1,w1h0,w1h1,w0h2,w2h0) accumulated in fp32 registers.
__global__ __launch_bounds__(256, 1) void score_mma_kernel(
    const float* __restrict__ score_b, float* __restrict__ out, int t, int out_size)
{
    extern __shared__ char dynsm[];

    const int tid  = threadIdx.x;
    const int wid  = tid >> 5;
    const int lane = tid & 31;
    const int n0   = blockIdx.x * VT;

    const uint32_t dbase = (smem_u32(dynsm) + 1023u) & ~1023u;

    const __nv_bfloat16* wpart[3] = { g_w0, g_w1, g_w2 };
    const __nv_bfloat16* hpart[3] = { g_h0, g_h1, g_h2 };

    // stage loader: 4608 16B segments (A: 3x128x8, B: 3x64x8), swizzled
    auto load_chunk = [&](int kc, int stg) {
#pragma unroll
        for (int i = 0; i < 18; i++) {
            int seg = tid + 256 * i;
            const __nv_bfloat16* src;
            uint32_t dst;
            const uint32_t sbase = dbase + stg * STAGE_BYTES;
            if (seg < 3072) {
                int p = seg >> 10, rem = seg & 1023;
                int r = rem >> 3, cb = rem & 7;
                src = wpart[p] + (((size_t)(n0 + r)) << 10) + (kc << 6) + (cb << 3);
                dst = sbase + p * A_PART + swz((uint32_t)(r * 128 + cb * 16));
            } else {
                int s2 = seg - 3072;
                int p = s2 >> 9, rem = s2 & 511;
                int r = rem >> 3, cb = rem & 7;
                src = hpart[p] + (r << 10) + (kc << 6) + (cb << 3);
                dst = sbase + A_REGION + p * B_PART + swz((uint32_t)(r * 128 + cb * 16));
            }
            cpa16(dst, src);
        }
        cpa_commit();
    };

    float acc[8][4];
#pragma unroll
    for (int j = 0; j < 8; j++)
#pragma unroll
        for (int q = 0; q < 4; q++) acc[j][q] = 0.0f;

    load_chunk(0, 0);
    load_chunk(1, 1);
    load_chunk(2, 2);

    // per-lane ldmatrix addressing components
    const int arow = 16 * wid + (lane & 15);       // A: tiles m0/m1 rows 0-15
    const int asel = (lane >> 4) & 1;              // m2/m3 -> k-high 16B chunk
    const int brow = ((lane & 16) ? 8 : 0) + (lane & 7);  // B: n within 16-col pair
    const int bsel = (lane >> 3) & 1;              // k-high chunk for m1/m3

    const int PI[6] = {0, 0, 1, 1, 0, 2};
    const int PJ[6] = {0, 1, 0, 1, 2, 0};

    int s = 0;
    for (int c = 0; c < NCH; c++) {
        if (c >= NCH - 1)      cpa_wait<0>();
        else if (c == NCH - 2) cpa_wait<1>();
        else                   cpa_wait<2>();
        __syncthreads();

        const uint32_t sbase = dbase + s * STAGE_BYTES;
#pragma unroll
        for (int pr = 0; pr < 6; pr++) {
            const uint32_t abase = sbase + PI[pr] * A_PART;
            const uint32_t bbase = sbase + A_REGION + PJ[pr] * B_PART;
#pragma unroll
            for (int kk = 0; kk < 4; kk++) {
                uint32_t a[4];
                ldsm_x4(a, abase + swz((uint32_t)(arow * 128 + (kk * 2 + asel) * 16)));
#pragma unroll
                for (int jp = 0; jp < 4; jp++) {
                    uint32_t b[4];
                    ldsm_x4(b, bbase + swz((uint32_t)((jp * 16 + brow) * 128 + (kk * 2 + bsel) * 16)));
                    mma_bf16(acc[2 * jp + 0], a, b[0], b[1]);
                    mma_bf16(acc[2 * jp + 1], a, b[2], b[3]);
                }
            }
        }
        __syncthreads();
        if (c + N_STAGES < NCH) load_chunk(c + N_STAGES, s);
        s++; if (s == N_STAGES) s = 0;
    }

    // ---------------- epilogue ----------------
    float* red = (float*)(dynsm + (dbase - smem_u32(dynsm)));  // [128][65] reuse stage mem

    const int r1 = 16 * wid + (lane >> 2);
    const int r2 = r1 + 8;
    const float bias1 = score_b[n0 + r1];
    const float bias2 = score_b[n0 + r2];
#pragma unroll
    for (int j = 0; j < 8; j++) {
        int cc = j * 8 + (lane & 3) * 2;
        red[r1 * 65 + cc + 0] = acc[j][0] + bias1;
        red[r1 * 65 + cc + 1] = acc[j][1] + bias1;
        red[r2 * 65 + cc + 0] = acc[j][2] + bias2;
        red[r2 * 65 + cc + 1] = acc[j][3] + bias2;
    }
    __syncthreads();

    // coalesced scores write: thread -> (batch b, 32 consecutive v)
    {
        const int b  = tid >> 2;
        const int v0 = (tid & 3) * 32;
        const size_t obase = (size_t)b * Tt * Vv + (size_t)t * Vv + n0 + v0;
#pragma unroll 8
        for (int i = 0; i < 32; i++) out[obase + i] = red[(v0 + i) * 65 + b];
    }

    // argmax partials (ties -> lowest index)
    if (tid < Bsz) {
        const int b = tid;
        float bb = -3.4e38f;
        int   bi = 0x7fffffff;
#pragma unroll 8
        for (int r = 0; r < VT; r++) {
            float v2 = red[r * 65 + b];
            int   iv = n0 + r;
            if (v2 > bb || (v2 == bb && iv < bi)) { bb = v2; bi = iv; }
        }
        g_pval[b][blockIdx.x] = bb;
        g_pidx[b][blockIdx.x] = bi;
    }
}

// ---------------- argmax reduce -> next token + samples ----------------
__global__ __launch_bounds__(128) void argmax_kernel(float* __restrict__ out, int t, int out_size) {
    __shared__ float sv[128];
    __shared__ int   si[128];
    const int row = blockIdx.x;
    const int tid = threadIdx.x;

    float bv = -3.4e38f;
    int   bi = 0x7fffffff;
    for (int p = tid; p < NBLK_SCORE; p += 128) {
        float v = g_pval[row][p];
        int   i = g_pidx[row][p];
        if (v > bv || (v == bv && i < bi)) { bv = v; bi = i; }
    }
    sv[tid] = bv; si[tid] = bi;
    __syncthreads();
    for (int s = 64; s > 0; s >>= 1) {
        if (tid < s) {
            float v = sv[tid + s];
            int   i = si[tid + s];
            if (v > sv[tid] || (v == sv[tid] && i < si[tid])) { sv[tid] = v; si[tid] = i; }
        }
        __syncthreads();
    }
    if (tid == 0) {
        g_xt[row] = si[0];
        long long off = (long long)Bsz * Tt * Vv + (long long)row * Tt + t;
        if (off < (long long)out_size) out[off] = (float)si[0];
    }
}

// ---------------- launch ----------------
extern "C" void kernel_launch(void* const* d_in, const int* in_sizes, int n_in,
                              void* d_out, int out_size) {
    const float* emb   = (const float*)d_in[0];
    const float* w_ih  = (const float*)d_in[1];
    const float* w_hh  = (const float*)d_in[2];
    const float* b_ih  = (const float*)d_in[3];
    const float* b_hh  = (const float*)d_in[4];
    const float* o2w   = (const float*)d_in[5];
    const float* o2b   = (const float*)d_in[6];
    const float* sw    = (const float*)d_in[7];
    const float* sb    = (const float*)d_in[8];
    float* out = (float*)d_out;
    (void)in_sizes; (void)n_in;

    cudaFuncSetAttribute(score_mma_kernel, cudaFuncAttributeMaxDynamicSharedMemorySize, DYN_BYTES);

    init_kernel<<<512, 256>>>();
    split_w_kernel<<<2048, 256>>>(sw);
    for (int t = 0; t < Tt; t++) {
        int parity = t & 1;
        lstm_kernel<<<128, 256>>>(emb, w_ih, w_hh, b_ih, b_hh, 0, parity);
        lstm_kernel<<<128, 256>>>(emb, w_ih, w_hh, b_ih, b_hh, 1, parity);
        o2emb_kernel<<<128, 128>>>(o2w, o2b, parity);
        score_mma_kernel<<<NBLK_SCORE, 256, DYN_BYTES>>>(sb, out, t, out_size);
        argmax_kernel<<<Bsz, 128>>>(out, t, out_size);
    }
}

// round 10
// speedup vs baseline: 3.4152x; 1.1475x over previous
#include <cuda_runtime.h>
#include <cuda_bf16.h>
#include <math.h>
#include <stdint.h>

#define Bsz 64
#define Hd  1024
#define Ed  1024
#define Vv  32000
#define Ll  2
#define Tt  64
#define START_TOK 1

#define BK 32
#define XPAD 34
#define VT 128                        // vocab rows per score tile
#define NBLK_SCORE (Vv / VT)          // 250
#define KC 64                         // bf16 K elems per chunk (128B rows)
#define NCH (Hd / KC)                 // 16 chunks
#define A_PART 16384                  // 128 rows * 128B
#define B_PART 8192                   // 64 rows * 128B
#define A_REGION (3 * A_PART)         // 49152
#define STAGE_BYTES (A_REGION + 3 * B_PART)  // 73728
#define N_STAGES 3
#define DYN_BYTES (N_STAGES * STAGE_BYTES + 1024)

typedef unsigned long long ull;

// ---------------- persistent device state ----------------
__device__ float g_hbuf[2][Ll][Bsz][Hd];
__device__ float g_cbuf[Ll][Bsz][Hd];
__device__ int   g_xt[Bsz];
__device__ float g_pval[Bsz][NBLK_SCORE];
__device__ int   g_pidx[Bsz][NBLK_SCORE];
__device__ float g_gpart[4][4][Bsz][Hd];   // [k-slice][gate][row][j] LSTM partials
__device__ float g_opart[2][Bsz][Ed];      // o2emb partials

// bf16 3-way splits (scratch)
__device__ __nv_bfloat16 g_w0[(size_t)Vv * Ed];
__device__ __nv_bfloat16 g_w1[(size_t)Vv * Ed];
__device__ __nv_bfloat16 g_w2[(size_t)Vv * Ed];
__device__ __nv_bfloat16 g_h0[Bsz * Ed];
__device__ __nv_bfloat16 g_h1[Bsz * Ed];
__device__ __nv_bfloat16 g_h2[Bsz * Ed];

// ---------------- helpers ----------------
__device__ __forceinline__ void ffma2(ull &acc, ull a, ull b) {
    asm("fma.rn.f32x2 %0, %1, %2, %0;" : "+l"(acc) : "l"(a), "l"(b));
}
__device__ __forceinline__ float fsum2(ull v) {
    return __uint_as_float((unsigned)v) + __uint_as_float((unsigned)(v >> 32));
}
__device__ __forceinline__ float sigmoidf_(float x) { return 1.0f / (1.0f + expf(-x)); }

__device__ __forceinline__ uint32_t smem_u32(const void* p) {
    uint32_t a;
    asm("{ .reg .u64 t; cvta.to.shared.u64 t, %1; cvt.u32.u64 %0, t; }" : "=r"(a) : "l"(p));
    return a;
}
__device__ __forceinline__ void cpa16(uint32_t dst, const void* src) {
    asm volatile("cp.async.cg.shared.global [%0], [%1], 16;" :: "r"(dst), "l"(src) : "memory");
}
__device__ __forceinline__ void cpa_commit() {
    asm volatile("cp.async.commit_group;" ::: "memory");
}
template <int N> __device__ __forceinline__ void cpa_wait() {
    asm volatile("cp.async.wait_group %0;" :: "n"(N) : "memory");
}
__device__ __forceinline__ void ldsm_x4(uint32_t* r, uint32_t addr) {
    asm volatile("ldmatrix.sync.aligned.m8n8.x4.shared.b16 {%0,%1,%2,%3}, [%4];"
                 : "=r"(r[0]), "=r"(r[1]), "=r"(r[2]), "=r"(r[3]) : "r"(addr));
}
__device__ __forceinline__ void mma_bf16(float* d, const uint32_t* a, uint32_t b0, uint32_t b1) {
    asm volatile(
        "mma.sync.aligned.m16n8k16.row.col.f32.bf16.bf16.f32 "
        "{%0,%1,%2,%3}, {%4,%5,%6,%7}, {%8,%9}, {%0,%1,%2,%3};"
        : "+f"(d[0]), "+f"(d[1]), "+f"(d[2]), "+f"(d[3])
        : "r"(a[0]), "r"(a[1]), "r"(a[2]), "r"(a[3]), "r"(b0), "r"(b1));
}
__device__ __forceinline__ uint32_t swz(uint32_t off) { return off ^ ((off >> 3) & 0x70); }

// ---------------- init ----------------
__global__ void init_kernel() {
    int idx = blockIdx.x * blockDim.x + threadIdx.x;
    float* c = &g_cbuf[0][0][0];
    float* h = &g_hbuf[0][0][0][0];
    if (idx < Ll * Bsz * Hd) { c[idx] = 0.0f; h[idx] = 0.0f; }
    if (idx < Bsz) g_xt[idx] = START_TOK;
}

// ---------------- weight split (once per launch) ----------------
__global__ __launch_bounds__(256) void split_w_kernel(const float* __restrict__ sw) {
    const size_t n = (size_t)Vv * Ed;
    for (size_t i = blockIdx.x * 256ull + threadIdx.x; i < n; i += (size_t)gridDim.x * 256ull) {
        float w = sw[i];
        __nv_bfloat16 a = __float2bfloat16(w);
        float r1 = w - __bfloat162float(a);
        __nv_bfloat16 b = __float2bfloat16(r1);
        float r2 = r1 - __bfloat162float(b);
        g_w0[i] = a; g_w1[i] = b; g_w2[i] = __float2bfloat16(r2);
    }
}

// ---------------- LSTM partial GEMM (K-split x4) ----------------
// grid = (128 j-blocks, 4 k-slices), 256 threads. Slices 0-1: w_ih pass; 2-3: w_hh pass.
// Thread tile: 2 rows x 4 gates of one j. Writes fp32 partials to g_gpart.
__global__ __launch_bounds__(256) void lstm_part_kernel(
    const float* __restrict__ emb,
    const float* __restrict__ w_ih_all, const float* __restrict__ w_hh_all,
    int layer, int parity)
{
    __shared__ float xs[Bsz][XPAD];
    __shared__ float ws[32][XPAD];

    const int tid   = threadIdx.x;
    const int j0    = blockIdx.x * 8;
    const int slice = blockIdx.y;
    const int cg    = tid & 7;
    const int rg    = tid >> 3;
    const int wp    = parity ^ 1;

    const float* wmat = (slice < 2)
        ? w_ih_all + (size_t)layer * 4 * Hd * Hd
        : w_hh_all + (size_t)layer * 4 * Hd * Hd;
    const int koff = (slice & 1) * 512;

    auto xrow = [&](int chunk, int r) -> const float* {
        int k0 = koff + chunk * BK;
        if (slice < 2) {
            if (layer == 0) return &emb[(size_t)g_xt[r] * Ed + k0];
            return &g_hbuf[wp][0][r][k0];
        }
        return &g_hbuf[parity][layer][r][k0];
    };

    ull acc[2][4];
#pragma unroll
    for (int i = 0; i < 2; i++)
#pragma unroll
        for (int g = 0; g < 4; g++) acc[i][g] = 0ULL;

    float4 px[2], pw;
    {
#pragma unroll
        for (int i = 0; i < 2; i++) {
            int item = tid + 256 * i;
            int r = item >> 3, c4 = item & 7;
            px[i] = *(const float4*)(xrow(0, r) + 4 * c4);
        }
        int c = tid >> 3, c4 = tid & 7;
        int n = ((c >> 3) << 10) + j0 + (c & 7);
        pw = *(const float4*)&wmat[(size_t)n * Hd + koff + 4 * c4];
    }

    const int NCHU = 512 / BK;   // 16
    for (int chunk = 0; chunk < NCHU; chunk++) {
#pragma unroll
        for (int i = 0; i < 2; i++) {
            int item = tid + 256 * i;
            int r = item >> 3, c4 = item & 7;
            xs[r][4 * c4 + 0] = px[i].x; xs[r][4 * c4 + 1] = px[i].y;
            xs[r][4 * c4 + 2] = px[i].z; xs[r][4 * c4 + 3] = px[i].w;
        }
        {
            int c = tid >> 3, c4 = tid & 7;
            ws[c][4 * c4 + 0] = pw.x; ws[c][4 * c4 + 1] = pw.y;
            ws[c][4 * c4 + 2] = pw.z; ws[c][4 * c4 + 3] = pw.w;
        }
        __syncthreads();

        if (chunk + 1 < NCHU) {
            int nc = chunk + 1;
#pragma unroll
            for (int i = 0; i < 2; i++) {
                int item = tid + 256 * i;
                int r = item >> 3, c4 = item & 7;
                px[i] = *(const float4*)(xrow(nc, r) + 4 * c4);
            }
            int c = tid >> 3, c4 = tid & 7;
            int n = ((c >> 3) << 10) + j0 + (c & 7);
            pw = *(const float4*)&wmat[(size_t)n * Hd + koff + nc * BK + 4 * c4];
        }

#pragma unroll
        for (int k2 = 0; k2 < BK / 2; k2++) {
            ull xv0 = *(const ull*)&xs[2 * rg + 0][2 * k2];
            ull xv1 = *(const ull*)&xs[2 * rg + 1][2 * k2];
#pragma unroll
            for (int g = 0; g < 4; g++) {
                ull wv = *(const ull*)&ws[g * 8 + cg][2 * k2];
                ffma2(acc[0][g], xv0, wv);
                ffma2(acc[1][g], xv1, wv);
            }
        }
        __syncthreads();
    }

    const int j = j0 + cg;
#pragma unroll
    for (int i = 0; i < 2; i++) {
        int row = 2 * rg + i;
#pragma unroll
        for (int g = 0; g < 4; g++)
            g_gpart[slice][g][row][j] = fsum2(acc[i][g]);
    }
}

// ---------------- LSTM cell update: reduce partials + biases, update c/h ----------------
__global__ __launch_bounds__(256) void lstm_cell_kernel(
    const float* __restrict__ b_ih_all, const float* __restrict__ b_hh_all,
    int layer, int parity)
{
    const int idx = blockIdx.x * 256 + threadIdx.x;   // 65536 total
    const int j   = idx & (Hd - 1);
    const int row = idx >> 10;
    const int wp  = parity ^ 1;

    float gi = b_ih_all[layer * 4 * Hd + 0 * Hd + j] + b_hh_all[layer * 4 * Hd + 0 * Hd + j];
    float gf = b_ih_all[layer * 4 * Hd + 1 * Hd + j] + b_hh_all[layer * 4 * Hd + 1 * Hd + j];
    float gg = b_ih_all[layer * 4 * Hd + 2 * Hd + j] + b_hh_all[layer * 4 * Hd + 2 * Hd + j];
    float go = b_ih_all[layer * 4 * Hd + 3 * Hd + j] + b_hh_all[layer * 4 * Hd + 3 * Hd + j];
#pragma unroll
    for (int s = 0; s < 4; s++) {
        gi += g_gpart[s][0][row][j];
        gf += g_gpart[s][1][row][j];
        gg += g_gpart[s][2][row][j];
        go += g_gpart[s][3][row][j];
    }
    float cold = g_cbuf[layer][row][j];
    float cnew = sigmoidf_(gf) * cold + sigmoidf_(gi) * tanhf(gg);
    float hnew = sigmoidf_(go) * tanhf(cnew);
    g_cbuf[layer][row][j]     = cnew;
    g_hbuf[wp][layer][row][j] = hnew;
}

// ---------------- o2emb partial GEMM (K-split x2) ----------------
// grid = (128 col-blocks, 2 k-slices), 128 threads, thread tile 4 rows x 1 col.
__global__ __launch_bounds__(128) void o2emb_part_kernel(
    const float* __restrict__ o2w, int parity)
{
    __shared__ float xs[Bsz][XPAD];
    __shared__ float ws[8][XPAD];

    const int tid   = threadIdx.x;
    const int n0    = blockIdx.x * 8;
    const int slice = blockIdx.y;
    const int koff  = slice * 512;
    const int cg    = tid & 7;
    const int rg    = tid >> 3;
    const int wp    = parity ^ 1;
    const float* xsrc = &g_hbuf[wp][Ll - 1][0][0];

    ull acc[4];
#pragma unroll
    for (int i = 0; i < 4; i++) acc[i] = 0ULL;

    float4 px[4], pw;
    {
#pragma unroll
        for (int i = 0; i < 4; i++) {
            int item = tid + 128 * i;
            int r = item >> 3, c4 = item & 7;
            px[i] = *(const float4*)&xsrc[r * Hd + koff + 4 * c4];
        }
        if (tid < 64) {
            int c = tid >> 3, c4 = tid & 7;
            pw = *(const float4*)&o2w[(size_t)(n0 + c) * Hd + koff + 4 * c4];
        }
    }

    const int NCHU = 512 / BK;   // 16
    for (int chunk = 0; chunk < NCHU; chunk++) {
#pragma unroll
        for (int i = 0; i < 4; i++) {
            int item = tid + 128 * i;
            int r = item >> 3, c4 = item & 7;
            xs[r][4 * c4 + 0] = px[i].x; xs[r][4 * c4 + 1] = px[i].y;
            xs[r][4 * c4 + 2] = px[i].z; xs[r][4 * c4 + 3] = px[i].w;
        }
        if (tid < 64) {
            int c = tid >> 3, c4 = tid & 7;
            ws[c][4 * c4 + 0] = pw.x; ws[c][4 * c4 + 1] = pw.y;
            ws[c][4 * c4 + 2] = pw.z; ws[c][4 * c4 + 3] = pw.w;
        }
        __syncthreads();

        if (chunk + 1 < NCHU) {
            int k0 = koff + (chunk + 1) * BK;
#pragma unroll
            for (int i = 0; i < 4; i++) {
                int item = tid + 128 * i;
                int r = item >> 3, c4 = item & 7;
                px[i] = *(const float4*)&xsrc[r * Hd + k0 + 4 * c4];
            }
            if (tid < 64) {
                int c = tid >> 3, c4 = tid & 7;
                pw = *(const float4*)&o2w[(size_t)(n0 + c) * Hd + k0 + 4 * c4];
            }
        }

#pragma unroll
        for (int k2 = 0; k2 < BK / 2; k2++) {
            ull wv = *(const ull*)&ws[cg][2 * k2];
#pragma unroll
            for (int i = 0; i < 4; i++) {
                ull xv = *(const ull*)&xs[4 * rg + i][2 * k2];
                ffma2(acc[i], xv, wv);
            }
        }
        __syncthreads();
    }

    const int n = n0 + cg;
#pragma unroll
    for (int i = 0; i < 4; i++)
        g_opart[slice][4 * rg + i][n] = fsum2(acc[i]);
}

// ---------------- o2emb combine: sum partials + bias, relu, bf16x3 split ----------------
__global__ __launch_bounds__(256) void o2emb_comb_kernel(const float* __restrict__ o2b) {
    const int idx = blockIdx.x * 256 + threadIdx.x;   // 65536 total
    const int n   = idx & (Ed - 1);
    const int row = idx >> 10;
    float v = g_opart[0][row][n] + g_opart[1][row][n] + o2b[n];
    v = v > 0.0f ? v : 0.0f;
    __nv_bfloat16 p0 = __float2bfloat16(v);
    float r1 = v - __bfloat162float(p0);
    __nv_bfloat16 p1 = __float2bfloat16(r1);
    float r2 = r1 - __bfloat162float(p1);
    g_h0[idx] = p0; g_h1[idx] = p1; g_h2[idx] = __float2bfloat16(r2);
}

// ---------------- score via mma.sync bf16x3 (B-fragment reuse) ----------------
// 250 CTAs x 256 threads (8 warps). Warp w owns vocab rows [16w,16w+16), 64 batch cols.
// Products: B0 pairs with {A0,A1,A2}, B1 with {A0,A1}, B2 with {A0}.
__global__ __launch_bounds__(256, 1) void score_mma_kernel(
    const float* __restrict__ score_b, float* __restrict__ out, int t, int out_size)
{
    extern __shared__ char dynsm[];

    const int tid  = threadIdx.x;
    const int wid  = tid >> 5;
    const int lane = tid & 31;
    const int n0   = blockIdx.x * VT;

    const uint32_t dbase = (smem_u32(dynsm) + 1023u) & ~1023u;

    const __nv_bfloat16* wpart[3] = { g_w0, g_w1, g_w2 };
    const __nv_bfloat16* hpart[3] = { g_h0, g_h1, g_h2 };

    auto load_chunk = [&](int kc, int stg) {
#pragma unroll
        for (int i = 0; i < 18; i++) {
            int seg = tid + 256 * i;
            const __nv_bfloat16* src;
            uint32_t dst;
            const uint32_t sbase = dbase + stg * STAGE_BYTES;
            if (seg < 3072) {
                int p = seg >> 10, rem = seg & 1023;
                int r = rem >> 3, cb = rem & 7;
                src = wpart[p] + (((size_t)(n0 + r)) << 10) + (kc << 6) + (cb << 3);
                dst = sbase + p * A_PART + swz((uint32_t)(r * 128 + cb * 16));
            } else {
                int s2 = seg - 3072;
                int p = s2 >> 9, rem = s2 & 511;
                int r = rem >> 3, cb = rem & 7;
                src = hpart[p] + (r << 10) + (kc << 6) + (cb << 3);
                dst = sbase + A_REGION + p * B_PART + swz((uint32_t)(r * 128 + cb * 16));
            }
            cpa16(dst, src);
        }
        cpa_commit();
    };

    float acc[8][4];
#pragma unroll
    for (int j = 0; j < 8; j++)
#pragma unroll
        for (int q = 0; q < 4; q++) acc[j][q] = 0.0f;

    load_chunk(0, 0);
    load_chunk(1, 1);
    load_chunk(2, 2);

    const int arow = 16 * wid + (lane & 15);
    const int asel = (lane >> 4) & 1;
    const int brow = ((lane & 16) ? 8 : 0) + (lane & 7);
    const int bsel = (lane >> 3) & 1;

    int s = 0;
    for (int c = 0; c < NCH; c++) {
        if (c >= NCH - 1)      cpa_wait<0>();
        else if (c == NCH - 2) cpa_wait<1>();
        else                   cpa_wait<2>();
        __syncthreads();

        const uint32_t sbase = dbase + s * STAGE_BYTES;
        const uint32_t bb0 = sbase + A_REGION;
#pragma unroll
        for (int kk = 0; kk < 4; kk++) {
            const uint32_t aoff = swz((uint32_t)(arow * 128 + (kk * 2 + asel) * 16));
            uint32_t a0[4], a1[4], a2[4];
            ldsm_x4(a0, sbase + 0 * A_PART + aoff);
            ldsm_x4(a1, sbase + 1 * A_PART + aoff);
            ldsm_x4(a2, sbase + 2 * A_PART + aoff);
#pragma unroll
            for (int jp = 0; jp < 4; jp++) {
                const uint32_t boff = swz((uint32_t)((jp * 16 + brow) * 128 + (kk * 2 + bsel) * 16));
                uint32_t b[4];
                // B part 0: pairs (w0,h0),(w1,h0),(w2,h0)
                ldsm_x4(b, bb0 + 0 * B_PART + boff);
                mma_bf16(acc[2 * jp + 0], a0, b[0], b[1]);
                mma_bf16(acc[2 * jp + 1], a0, b[2], b[3]);
                mma_bf16(acc[2 * jp + 0], a1, b[0], b[1]);
                mma_bf16(acc[2 * jp + 1], a1, b[2], b[3]);
                mma_bf16(acc[2 * jp + 0], a2, b[0], b[1]);
                mma_bf16(acc[2 * jp + 1], a2, b[2], b[3]);
                // B part 1: pairs (w0,h1),(w1,h1)
                ldsm_x4(b, bb0 + 1 * B_PART + boff);
                mma_bf16(acc[2 * jp + 0], a0, b[0], b[1]);
                mma_bf16(acc[2 * jp + 1], a0, b[2], b[3]);
                mma_bf16(acc[2 * jp + 0], a1, b[0], b[1]);
                mma_bf16(acc[2 * jp + 1], a1, b[2], b[3]);
                // B part 2: pair (w0,h2)
                ldsm_x4(b, bb0 + 2 * B_PART + boff);
                mma_bf16(acc[2 * jp + 0], a0, b[0], b[1]);
                mma_bf16(acc[2 * jp + 1], a0, b[2], b[3]);
            }
        }
        __syncthreads();
        if (c + N_STAGES < NCH) load_chunk(c + N_STAGES, s);
        s++; if (s == N_STAGES) s = 0;
    }

    // ---------------- epilogue ----------------
    float* red = (float*)(dynsm + (dbase - smem_u32(dynsm)));  // [128][65]

    const int r1 = 16 * wid + (lane >> 2);
    const int r2 = r1 + 8;
    const float bias1 = score_b[n0 + r1];
    const float bias2 = score_b[n0 + r2];
#pragma unroll
    for (int j = 0; j < 8; j++) {
        int cc = j * 8 + (lane & 3) * 2;
        red[r1 * 65 + cc + 0] = acc[j][0] + bias1;
        red[r1 * 65 + cc + 1] = acc[j][1] + bias1;
        red[r2 * 65 + cc + 0] = acc[j][2] + bias2;
        red[r2 * 65 + cc + 1] = acc[j][3] + bias2;
    }
    __syncthreads();

    {
        const int b  = tid >> 2;
        const int v0 = (tid & 3) * 32;
        const size_t obase = (size_t)b * Tt * Vv + (size_t)t * Vv + n0 + v0;
#pragma unroll 8
        for (int i = 0; i < 32; i++) out[obase + i] = red[(v0 + i) * 65 + b];
    }

    if (tid < Bsz) {
        const int b = tid;
        float bb = -3.4e38f;
        int   bi = 0x7fffffff;
#pragma unroll 8
        for (int r = 0; r < VT; r++) {
            float v2 = red[r * 65 + b];
            int   iv = n0 + r;
            if (v2 > bb || (v2 == bb && iv < bi)) { bb = v2; bi = iv; }
        }
        g_pval[b][blockIdx.x] = bb;
        g_pidx[b][blockIdx.x] = bi;
    }
}

// ---------------- argmax reduce -> next token + samples ----------------
__global__ __launch_bounds__(128) void argmax_kernel(float* __restrict__ out, int t, int out_size) {
    __shared__ float sv[128];
    __shared__ int   si[128];
    const int row = blockIdx.x;
    const int tid = threadIdx.x;

    float bv = -3.4e38f;
    int   bi = 0x7fffffff;
    for (int p = tid; p < NBLK_SCORE; p += 128) {
        float v = g_pval[row][p];
        int   i = g_pidx[row][p];
        if (v > bv || (v == bv && i < bi)) { bv = v; bi = i; }
    }
    sv[tid] = bv; si[tid] = bi;
    __syncthreads();
    for (int s = 64; s > 0; s >>= 1) {
        if (tid < s) {
            float v = sv[tid + s];
            int   i = si[tid + s];
            if (v > sv[tid] || (v == sv[tid] && i < si[tid])) { sv[tid] = v; si[tid] = i; }
        }
        __syncthreads();
    }
    if (tid == 0) {
        g_xt[row] = si[0];
        long long off = (long long)Bsz * Tt * Vv + (long long)row * Tt + t;
        if (off < (long long)out_size) out[off] = (float)si[0];
    }
}

// ---------------- launch ----------------
extern "C" void kernel_launch(void* const* d_in, const int* in_sizes, int n_in,
                              void* d_out, int out_size) {
    const float* emb   = (const float*)d_in[0];
    const float* w_ih  = (const float*)d_in[1];
    const float* w_hh  = (const float*)d_in[2];
    const float* b_ih  = (const float*)d_in[3];
    const float* b_hh  = (const float*)d_in[4];
    const float* o2w   = (const float*)d_in[5];
    const float* o2b   = (const float*)d_in[6];
    const float* sw    = (const float*)d_in[7];
    const float* sb    = (const float*)d_in[8];
    float* out = (float*)d_out;
    (void)in_sizes; (void)n_in;

    cudaFuncSetAttribute(score_mma_kernel, cudaFuncAttributeMaxDynamicSharedMemorySize, DYN_BYTES);

    init_kernel<<<512, 256>>>();
    split_w_kernel<<<2048, 256>>>(sw);
    for (int t = 0; t < Tt; t++) {
        int parity = t & 1;
        lstm_part_kernel<<<dim3(128, 4), 256>>>(emb, w_ih, w_hh, 0, parity);
        lstm_cell_kernel<<<256, 256>>>(b_ih, b_hh, 0, parity);
        lstm_part_kernel<<<dim3(128, 4), 256>>>(emb, w_ih, w_hh, 1, parity);
        lstm_cell_kernel<<<256, 256>>>(b_ih, b_hh, 1, parity);
        o2emb_part_kernel<<<dim3(128, 2), 128>>>(o2w, parity);
        o2emb_comb_kernel<<<256, 256>>>(o2b);
        score_mma_kernel<<<NBLK_SCORE, 256, DYN_BYTES>>>(sb, out, t, out_size);
        argmax_kernel<<<Bsz, 128>>>(out, t, out_size);
    }
}

// round 12
// speedup vs baseline: 4.8093x; 1.4082x over previous
#include <cuda_runtime.h>
#include <cuda_fp16.h>
#include <math.h>
#include <stdint.h>

#define Bsz 64
#define Hd  1024
#define Ed  1024
#define Vv  32000
#define Ll  2
#define Tt  64
#define START_TOK 1

#define BK 32
#define XPAD 34
#define VT 128                        // rows per MMA tile
#define NBLK_SCORE (Vv / VT)          // 250
#define KC 64                         // fp16 K elems per chunk (128B rows)
#define NCH 16                        // score: 1024/64
#define NCH_L 8                       // lstm slice: 512/64
#define A_PART 16384                  // 128 rows * 128B
#define B_PART 8192                   // 64 rows * 128B
#define A_REGION (2 * A_PART)         // 32768 (2 fp16 parts)
#define B_REGION (2 * B_PART)         // 16384
#define STAGE_BYTES (A_REGION + B_REGION)  // 49152
#define N_STAGES 3
#define DYN_BYTES (N_STAGES * STAGE_BYTES + 1024)

typedef unsigned long long ull;

// ---------------- persistent device state ----------------
__device__ float  g_cbuf[Ll][Bsz][Hd];       // cell state
__device__ float  g_hfp[Ll][Bsz][Hd];        // h fp32 (o2emb input)
__device__ __half g_hs0[Ll][Bsz][Hd];        // h fp16 split hi
__device__ __half g_hs1[Ll][Bsz][Hd];        // h fp16 split lo
__device__ int    g_xt[Bsz];
__device__ float  g_pval[Bsz][NBLK_SCORE];
__device__ int    g_pidx[Bsz][NBLK_SCORE];
__device__ float  g_gpart[4][Bsz][4 * Hd];   // [k-slice][batch][gate-row n]
__device__ float  g_opart[2][Bsz][Ed];
__device__ int    g_cnt;

// fp16x2 splits (one-time)
__device__ __half g_w0[(size_t)Vv * Ed];     // score_w hi
__device__ __half g_w1[(size_t)Vv * Ed];     // score_w lo
__device__ __half g_e0[(size_t)Vv * Ed];     // emb hi
__device__ __half g_e1[(size_t)Vv * Ed];     // emb lo
__device__ __half g_lw0[Ll * 2 * 4 * Hd * Hd];  // [layer][ih/hh][4096][1024] hi
__device__ __half g_lw1[Ll * 2 * 4 * Hd * Hd];  // lo
// per-step splits
__device__ __half g_h0[Bsz * Ed];            // hid hi
__device__ __half g_h1[Bsz * Ed];            // hid lo

// ---------------- helpers ----------------
__device__ __forceinline__ void ffma2(ull &acc, ull a, ull b) {
    asm("fma.rn.f32x2 %0, %1, %2, %0;" : "+l"(acc) : "l"(a), "l"(b));
}
__device__ __forceinline__ float fsum2(ull v) {
    return __uint_as_float((unsigned)v) + __uint_as_float((unsigned)(v >> 32));
}
__device__ __forceinline__ float sigmoidf_(float x) { return 1.0f / (1.0f + expf(-x)); }

__device__ __forceinline__ uint32_t smem_u32(const void* p) {
    uint32_t a;
    asm("{ .reg .u64 t; cvta.to.shared.u64 t, %1; cvt.u32.u64 %0, t; }" : "=r"(a) : "l"(p));
    return a;
}
__device__ __forceinline__ void cpa16(uint32_t dst, const void* src) {
    asm volatile("cp.async.cg.shared.global [%0], [%1], 16;" :: "r"(dst), "l"(src) : "memory");
}
__device__ __forceinline__ void cpa_commit() {
    asm volatile("cp.async.commit_group;" ::: "memory");
}
template <int N> __device__ __forceinline__ void cpa_wait() {
    asm volatile("cp.async.wait_group %0;" :: "n"(N) : "memory");
}
__device__ __forceinline__ void ldsm_x4(uint32_t* r, uint32_t addr) {
    asm volatile("ldmatrix.sync.aligned.m8n8.x4.shared.b16 {%0,%1,%2,%3}, [%4];"
                 : "=r"(r[0]), "=r"(r[1]), "=r"(r[2]), "=r"(r[3]) : "r"(addr));
}
__device__ __forceinline__ void mma_f16(float* d, const uint32_t* a, uint32_t b0, uint32_t b1) {
    asm volatile(
        "mma.sync.aligned.m16n8k16.row.col.f32.f16.f16.f32 "
        "{%0,%1,%2,%3}, {%4,%5,%6,%7}, {%8,%9}, {%0,%1,%2,%3};"
        : "+f"(d[0]), "+f"(d[1]), "+f"(d[2]), "+f"(d[3])
        : "r"(a[0]), "r"(a[1]), "r"(a[2]), "r"(a[3]), "r"(b0), "r"(b1));
}
__device__ __forceinline__ uint32_t swz(uint32_t off) { return off ^ ((off >> 3) & 0x70); }

// ---------------- init ----------------
__global__ void init_kernel() {
    int idx = blockIdx.x * blockDim.x + threadIdx.x;
    if (idx < Ll * Bsz * Hd) {
        (&g_cbuf[0][0][0])[idx] = 0.0f;
        (&g_hs0[0][0][0])[idx] = __float2half_rn(0.0f);
        (&g_hs1[0][0][0])[idx] = __float2half_rn(0.0f);
    }
    if (idx < Bsz) g_xt[idx] = START_TOK;
    if (idx == 0) g_cnt = 0;
}

// ---------------- one-time fp16x2 splits ----------------
__global__ __launch_bounds__(256) void split_w_kernel(const float* __restrict__ sw,
                                                      const float* __restrict__ emb) {
    const size_t n = (size_t)Vv * Ed;
    for (size_t i = blockIdx.x * 256ull + threadIdx.x; i < n; i += (size_t)gridDim.x * 256ull) {
        float w = sw[i];
        __half a = __float2half_rn(w);
        g_w0[i] = a;
        g_w1[i] = __float2half_rn(w - __half2float(a));
        float e = emb[i];
        __half c = __float2half_rn(e);
        g_e0[i] = c;
        g_e1[i] = __float2half_rn(e - __half2float(c));
    }
}
__global__ __launch_bounds__(256) void split_lstm_kernel(const float* __restrict__ w_ih,
                                                         const float* __restrict__ w_hh) {
    const size_t n = (size_t)Ll * 2 * 4 * Hd * Hd;      // 16.8M
    const size_t per = (size_t)4 * Hd * Hd;             // 4.2M per matrix
    for (size_t i = blockIdx.x * 256ull + threadIdx.x; i < n; i += (size_t)gridDim.x * 256ull) {
        size_t mat = i / per;          // layer*2 + (0=ih,1=hh)
        size_t off = i % per;
        size_t layer = mat >> 1;
        float w = (mat & 1) ? w_hh[layer * per + off] : w_ih[layer * per + off];
        __half a = __float2half_rn(w);
        g_lw0[i] = a;
        g_lw1[i] = __float2half_rn(w - __half2float(a));
    }
}

// ---------------- LSTM partial GEMM via mma.sync fp16x2 ----------------
// grid = (32 gate-row tiles, 4 k-slices), 256 threads (8 warps x 16 rows).
// Slice s: matrix = (s>=2 ? hh : ih), k window = (s&1)*512.
// D[gate-row, batch] partials (3 products) -> g_gpart[slice].
__global__ __launch_bounds__(256, 1) void lstm_mma_kernel(int layer)
{
    extern __shared__ char dynsm[];
    const int tid  = threadIdx.x;
    const int wid  = tid >> 5;
    const int lane = tid & 31;
    const int n0   = blockIdx.x * VT;
    const int slice = blockIdx.y;
    const int koff = (slice & 1) * 512;
    const int m    = (slice >= 2) ? 1 : 0;

    const uint32_t dbase = (smem_u32(dynsm) + 1023u) & ~1023u;

    const __half* abase0 = g_lw0 + ((size_t)(layer * 2 + m) * 4 * Hd + n0) * Hd + koff;
    const __half* abase1 = g_lw1 + ((size_t)(layer * 2 + m) * 4 * Hd + n0) * Hd + koff;

    // B row base for (part p, batch r)
    auto bsrc = [&](int p, int r) -> const __half* {
        if (layer == 0) {
            if (slice < 2) return (p ? g_e1 : g_e0) + (size_t)g_xt[r] * Ed + koff;
            return &(p ? g_hs1 : g_hs0)[0][r][koff];
        } else {
            if (slice < 2) return &(p ? g_hs1 : g_hs0)[0][r][koff];
            return &(p ? g_hs1 : g_hs0)[1][r][koff];
        }
    };

    auto load_chunk = [&](int kc, int stg) {
        const uint32_t sbase = dbase + stg * STAGE_BYTES;
#pragma unroll
        for (int i = 0; i < 12; i++) {
            int seg = tid + 256 * i;
            const __half* src;
            uint32_t dst;
            if (seg < 2048) {
                int p = seg >> 10, rem = seg & 1023;
                int r = rem >> 3, cb = rem & 7;
                src = (p ? abase1 : abase0) + (size_t)r * Hd + kc * KC + cb * 8;
                dst = sbase + p * A_PART + swz((uint32_t)(r * 128 + cb * 16));
            } else {
                int s2 = seg - 2048;
                int p = s2 >> 9, rem = s2 & 511;
                int r = rem >> 3, cb = rem & 7;
                src = bsrc(p, r) + kc * KC + cb * 8;
                dst = sbase + A_REGION + p * B_PART + swz((uint32_t)(r * 128 + cb * 16));
            }
            cpa16(dst, src);
        }
        cpa_commit();
    };

    float acc[8][4];
#pragma unroll
    for (int j = 0; j < 8; j++)
#pragma unroll
        for (int q = 0; q < 4; q++) acc[j][q] = 0.0f;

    load_chunk(0, 0);
    load_chunk(1, 1);
    load_chunk(2, 2);

    const int arow = 16 * wid + (lane & 15);
    const int asel = (lane >> 4) & 1;
    const int brow = ((lane & 16) ? 8 : 0) + (lane & 7);
    const int bsel = (lane >> 3) & 1;

    int s = 0;
    for (int c = 0; c < NCH_L; c++) {
        if (c >= NCH_L - 1)      cpa_wait<0>();
        else if (c == NCH_L - 2) cpa_wait<1>();
        else                     cpa_wait<2>();
        __syncthreads();

        const uint32_t sbase = dbase + s * STAGE_BYTES;
        const uint32_t bb = sbase + A_REGION;
#pragma unroll
        for (int kk = 0; kk < 4; kk++) {
            const uint32_t aoff = swz((uint32_t)(arow * 128 + (kk * 2 + asel) * 16));
            uint32_t a0[4], a1[4];
            ldsm_x4(a0, sbase + 0 * A_PART + aoff);
            ldsm_x4(a1, sbase + 1 * A_PART + aoff);
#pragma unroll
            for (int jp = 0; jp < 4; jp++) {
                const uint32_t boff = swz((uint32_t)((jp * 16 + brow) * 128 + (kk * 2 + bsel) * 16));
                uint32_t b[4];
                ldsm_x4(b, bb + 0 * B_PART + boff);       // h0: (w0,h0),(w1,h0)
                mma_f16(acc[2 * jp + 0], a0, b[0], b[1]);
                mma_f16(acc[2 * jp + 1], a0, b[2], b[3]);
                mma_f16(acc[2 * jp + 0], a1, b[0], b[1]);
                mma_f16(acc[2 * jp + 1], a1, b[2], b[3]);
                ldsm_x4(b, bb + 1 * B_PART + boff);       // h1: (w0,h1)
                mma_f16(acc[2 * jp + 0], a0, b[0], b[1]);
                mma_f16(acc[2 * jp + 1], a0, b[2], b[3]);
            }
        }
        __syncthreads();
        if (c + N_STAGES < NCH_L) load_chunk(c + N_STAGES, s);
        s++; if (s == N_STAGES) s = 0;
    }

    // epilogue: smem transpose -> coalesced partial writes
    float* red = (float*)(dynsm + (dbase - smem_u32(dynsm)));   // [128][65]
    const int r1 = 16 * wid + (lane >> 2);
    const int r2 = r1 + 8;
#pragma unroll
    for (int j = 0; j < 8; j++) {
        int cc = j * 8 + (lane & 3) * 2;
        red[r1 * 65 + cc + 0] = acc[j][0];
        red[r1 * 65 + cc + 1] = acc[j][1];
        red[r2 * 65 + cc + 0] = acc[j][2];
        red[r2 * 65 + cc + 1] = acc[j][3];
    }
    __syncthreads();
    {
        const int b  = tid >> 2;
        const int v0 = (tid & 3) * 32;
#pragma unroll 8
        for (int i = 0; i < 32; i++)
            g_gpart[slice][b][n0 + v0 + i] = red[(v0 + i) * 65 + b];
    }
}

// ---------------- LSTM cell update: reduce partials + biases, update c/h, split h ----------------
__global__ __launch_bounds__(256) void lstm_cell_kernel(
    const float* __restrict__ b_ih_all, const float* __restrict__ b_hh_all, int layer)
{
    const int idx = blockIdx.x * 256 + threadIdx.x;   // 65536
    const int j   = idx & (Hd - 1);
    const int row = idx >> 10;

    float gi = b_ih_all[layer * 4 * Hd + 0 * Hd + j] + b_hh_all[layer * 4 * Hd + 0 * Hd + j];
    float gf = b_ih_all[layer * 4 * Hd + 1 * Hd + j] + b_hh_all[layer * 4 * Hd + 1 * Hd + j];
    float gg = b_ih_all[layer * 4 * Hd + 2 * Hd + j] + b_hh_all[layer * 4 * Hd + 2 * Hd + j];
    float go = b_ih_all[layer * 4 * Hd + 3 * Hd + j] + b_hh_all[layer * 4 * Hd + 3 * Hd + j];
#pragma unroll
    for (int s = 0; s < 4; s++) {
        gi += g_gpart[s][row][0 * Hd + j];
        gf += g_gpart[s][row][1 * Hd + j];
        gg += g_gpart[s][row][2 * Hd + j];
        go += g_gpart[s][row][3 * Hd + j];
    }
    float cold = g_cbuf[layer][row][j];
    float cnew = sigmoidf_(gf) * cold + sigmoidf_(gi) * tanhf(gg);
    float hnew = sigmoidf_(go) * tanhf(cnew);
    g_cbuf[layer][row][j] = cnew;
    g_hfp[layer][row][j]  = hnew;
    __half h0 = __float2half_rn(hnew);
    g_hs0[layer][row][j] = h0;
    g_hs1[layer][row][j] = __float2half_rn(hnew - __half2float(h0));
}

// ---------------- o2emb partial GEMM (scalar FFMA2, K-split x2) ----------------
__global__ __launch_bounds__(128) void o2emb_part_kernel(const float* __restrict__ o2w)
{
    __shared__ float xs[Bsz][XPAD];
    __shared__ float ws[8][XPAD];

    const int tid   = threadIdx.x;
    const int n0    = blockIdx.x * 8;
    const int slice = blockIdx.y;
    const int koff  = slice * 512;
    const int cg    = tid & 7;
    const int rg    = tid >> 3;
    const float* xsrc = &g_hfp[Ll - 1][0][0];

    ull acc[4];
#pragma unroll
    for (int i = 0; i < 4; i++) acc[i] = 0ULL;

    float4 px[4], pw;
    {
#pragma unroll
        for (int i = 0; i < 4; i++) {
            int item = tid + 128 * i;
            int r = item >> 3, c4 = item & 7;
            px[i] = *(const float4*)&xsrc[r * Hd + koff + 4 * c4];
        }
        if (tid < 64) {
            int c = tid >> 3, c4 = tid & 7;
            pw = *(const float4*)&o2w[(size_t)(n0 + c) * Hd + koff + 4 * c4];
        }
    }

    const int NCHU = 512 / BK;   // 16
    for (int chunk = 0; chunk < NCHU; chunk++) {
#pragma unroll
        for (int i = 0; i < 4; i++) {
            int item = tid + 128 * i;
            int r = item >> 3, c4 = item & 7;
            xs[r][4 * c4 + 0] = px[i].x; xs[r][4 * c4 + 1] = px[i].y;
            xs[r][4 * c4 + 2] = px[i].z; xs[r][4 * c4 + 3] = px[i].w;
        }
        if (tid < 64) {
            int c = tid >> 3, c4 = tid & 7;
            ws[c][4 * c4 + 0] = pw.x; ws[c][4 * c4 + 1] = pw.y;
            ws[c][4 * c4 + 2] = pw.z; ws[c][4 * c4 + 3] = pw.w;
        }
        __syncthreads();

        if (chunk + 1 < NCHU) {
            int k0 = koff + (chunk + 1) * BK;
#pragma unroll
            for (int i = 0; i < 4; i++) {
                int item = tid + 128 * i;
                int r = item >> 3, c4 = item & 7;
                px[i] = *(const float4*)&xsrc[r * Hd + k0 + 4 * c4];
            }
            if (tid < 64) {
                int c = tid >> 3, c4 = tid & 7;
                pw = *(const float4*)&o2w[(size_t)(n0 + c) * Hd + k0 + 4 * c4];
            }
        }

#pragma unroll
        for (int k2 = 0; k2 < BK / 2; k2++) {
            ull wv = *(const ull*)&ws[cg][2 * k2];
#pragma unroll
            for (int i = 0; i < 4; i++) {
                ull xv = *(const ull*)&xs[4 * rg + i][2 * k2];
                ffma2(acc[i], xv, wv);
            }
        }
        __syncthreads();
    }

    const int n = n0 + cg;
#pragma unroll
    for (int i = 0; i < 4; i++)
        g_opart[slice][4 * rg + i][n] = fsum2(acc[i]);
}

// ---------------- o2emb combine: bias + relu -> fp16x2 split ----------------
__global__ __launch_bounds__(256) void o2emb_comb_kernel(const float* __restrict__ o2b) {
    const int idx = blockIdx.x * 256 + threadIdx.x;   // 65536
    const int n   = idx & (Ed - 1);
    const int row = idx >> 10;
    float v = g_opart[0][row][n] + g_opart[1][row][n] + o2b[n];
    v = v > 0.0f ? v : 0.0f;
    __half p0 = __float2half_rn(v);
    g_h0[idx] = p0;
    g_h1[idx] = __float2half_rn(v - __half2float(p0));
}

// ---------------- score via mma.sync fp16x2 + fused final argmax ----------------
__global__ __launch_bounds__(256, 1) void score_mma_kernel(
    const float* __restrict__ score_b, float* __restrict__ out, int t, int out_size)
{
    extern __shared__ char dynsm[];
    __shared__ bool amLast;

    const int tid  = threadIdx.x;
    const int wid  = tid >> 5;
    const int lane = tid & 31;
    const int n0   = blockIdx.x * VT;

    const uint32_t dbase = (smem_u32(dynsm) + 1023u) & ~1023u;

    auto load_chunk = [&](int kc, int stg) {
        const uint32_t sbase = dbase + stg * STAGE_BYTES;
#pragma unroll
        for (int i = 0; i < 12; i++) {
            int seg = tid + 256 * i;
            const __half* src;
            uint32_t dst;
            if (seg < 2048) {
                int p = seg >> 10, rem = seg & 1023;
                int r = rem >> 3, cb = rem & 7;
                src = (p ? g_w1 : g_w0) + (((size_t)(n0 + r)) << 10) + kc * KC + cb * 8;
                dst = sbase + p * A_PART + swz((uint32_t)(r * 128 + cb * 16));
            } else {
                int s2 = seg - 2048;
                int p = s2 >> 9, rem = s2 & 511;
                int r = rem >> 3, cb = rem & 7;
                src = (p ? g_h1 : g_h0) + (r << 10) + kc * KC + cb * 8;
                dst = sbase + A_REGION + p * B_PART + swz((uint32_t)(r * 128 + cb * 16));
            }
            cpa16(dst, src);
        }
        cpa_commit();
    };

    float acc[8][4];
#pragma unroll
    for (int j = 0; j < 8; j++)
#pragma unroll
        for (int q = 0; q < 4; q++) acc[j][q] = 0.0f;

    load_chunk(0, 0);
    load_chunk(1, 1);
    load_chunk(2, 2);

    const int arow = 16 * wid + (lane & 15);
    const int asel = (lane >> 4) & 1;
    const int brow = ((lane & 16) ? 8 : 0) + (lane & 7);
    const int bsel = (lane >> 3) & 1;

    int s = 0;
    for (int c = 0; c < NCH; c++) {
        if (c >= NCH - 1)      cpa_wait<0>();
        else if (c == NCH - 2) cpa_wait<1>();
        else                   cpa_wait<2>();
        __syncthreads();

        const uint32_t sbase = dbase + s * STAGE_BYTES;
        const uint32_t bb = sbase + A_REGION;
#pragma unroll
        for (int kk = 0; kk < 4; kk++) {
            const uint32_t aoff = swz((uint32_t)(arow * 128 + (kk * 2 + asel) * 16));
            uint32_t a0[4], a1[4];
            ldsm_x4(a0, sbase + 0 * A_PART + aoff);
            ldsm_x4(a1, sbase + 1 * A_PART + aoff);
#pragma unroll
            for (int jp = 0; jp < 4; jp++) {
                const uint32_t boff = swz((uint32_t)((jp * 16 + brow) * 128 + (kk * 2 + bsel) * 16));
                uint32_t b[4];
                ldsm_x4(b, bb + 0 * B_PART + boff);
                mma_f16(acc[2 * jp + 0], a0, b[0], b[1]);
                mma_f16(acc[2 * jp + 1], a0, b[2], b[3]);
                mma_f16(acc[2 * jp + 0], a1, b[0], b[1]);
                mma_f16(acc[2 * jp + 1], a1, b[2], b[3]);
                ldsm_x4(b, bb + 1 * B_PART + boff);
                mma_f16(acc[2 * jp + 0], a0, b[0], b[1]);
                mma_f16(acc[2 * jp + 1], a0, b[2], b[3]);
            }
        }
        __syncthreads();
        if (c + N_STAGES < NCH) load_chunk(c + N_STAGES, s);
        s++; if (s == N_STAGES) s = 0;
    }

    // ---------------- epilogue ----------------
    float* red = (float*)(dynsm + (dbase - smem_u32(dynsm)));  // [128][65]

    const int r1 = 16 * wid + (lane >> 2);
    const int r2 = r1 + 8;
    const float bias1 = score_b[n0 + r1];
    const float bias2 = score_b[n0 + r2];
#pragma unroll
    for (int j = 0; j < 8; j++) {
        int cc = j * 8 + (lane & 3) * 2;
        red[r1 * 65 + cc + 0] = acc[j][0] + bias1;
        red[r1 * 65 + cc + 1] = acc[j][1] + bias1;
        red[r2 * 65 + cc + 0] = acc[j][2] + bias2;
        red[r2 * 65 + cc + 1] = acc[j][3] + bias2;
    }
    __syncthreads();

    {
        const int b  = tid >> 2;
        const int v0 = (tid & 3) * 32;
        const size_t obase = (size_t)b * Tt * Vv + (size_t)t * Vv + n0 + v0;
#pragma unroll 8
        for (int i = 0; i < 32; i++) out[obase + i] = red[(v0 + i) * 65 + b];
    }

    if (tid < Bsz) {
        const int b = tid;
        float bb = -3.4e38f;
        int   bi = 0x7fffffff;
#pragma unroll 8
        for (int r = 0; r < VT; r++) {
            float v2 = red[r * 65 + b];
            int   iv = n0 + r;
            if (v2 > bb || (v2 == bb && iv < bi)) { bb = v2; bi = iv; }
        }
        g_pval[b][blockIdx.x] = bb;
        g_pidx[b][blockIdx.x] = bi;
    }
    __syncthreads();

    // last-CTA final argmax (release/acquire via threadfence + atomic)
    if (tid == 0) {
        __threadfence();
        int old = atomicAdd(&g_cnt, 1);
        amLast = (old == NBLK_SCORE - 1);
    }
    __syncthreads();
    if (amLast) {
        __threadfence();
        if (tid < Bsz) {
            const int b = tid;
            float bv = -3.4e38f;
            int   bi = 0x7fffffff;
#pragma unroll 5
            for (int p = 0; p < NBLK_SCORE; p++) {
                float v = g_pval[b][p];
                int   i = g_pidx[b][p];
                if (v > bv || (v == bv && i < bi)) { bv = v; bi = i; }
            }
            g_xt[b] = bi;
            long long off = (long long)Bsz * Tt * Vv + (long long)b * Tt + t;
            if (off < (long long)out_size) out[off] = (float)bi;
        }
        if (tid == 0) g_cnt = 0;   // reset for next launch
    }
}

// ---------------- launch ----------------
extern "C" void kernel_launch(void* const* d_in, const int* in_sizes, int n_in,
                              void* d_out, int out_size) {
    const float* emb   = (const float*)d_in[0];
    const float* w_ih  = (const float*)d_in[1];
    const float* w_hh  = (const float*)d_in[2];
    const float* b_ih  = (const float*)d_in[3];
    const float* b_hh  = (const float*)d_in[4];
    const float* o2w   = (const float*)d_in[5];
    const float* o2b   = (const float*)d_in[6];
    const float* sw    = (const float*)d_in[7];
    const float* sb    = (const float*)d_in[8];
    float* out = (float*)d_out;
    (void)in_sizes; (void)n_in;

    cudaFuncSetAttribute(score_mma_kernel, cudaFuncAttributeMaxDynamicSharedMemorySize, DYN_BYTES);
    cudaFuncSetAttribute(lstm_mma_kernel, cudaFuncAttributeMaxDynamicSharedMemorySize, DYN_BYTES);

    init_kernel<<<512, 256>>>();
    split_w_kernel<<<2048, 256>>>(sw, emb);
    split_lstm_kernel<<<2048, 256>>>(w_ih, w_hh);
    for (int t = 0; t < Tt; t++) {
        lstm_mma_kernel<<<dim3(32, 4), 256, DYN_BYTES>>>(0);
        lstm_cell_kernel<<<256, 256>>>(b_ih, b_hh, 0);
        lstm_mma_kernel<<<dim3(32, 4), 256, DYN_BYTES>>>(1);
        lstm_cell_kernel<<<256, 256>>>(b_ih, b_hh, 1);
        o2emb_part_kernel<<<dim3(128, 2), 128>>>(o2w);
        o2emb_comb_kernel<<<256, 256>>>(o2b);
        score_mma_kernel<<<NBLK_SCORE, 256, DYN_BYTES>>>(sb, out, t, out_size);
    }
}